// round 1
// baseline (speedup 1.0000x reference)
#include <cuda_runtime.h>
#include <math.h>

// Problem dims
#define BATCH   8
#define SEQ     1024
#define DMODEL  1152
#define NHEAD   16
#define HDIM    72
#define SENC    77
#define FFD     4608
#define ROWS    (BATCH*SEQ)        // 8192
#define ENCROWS (BATCH*SENC)       // 616
#define BH      (BATCH*NHEAD)      // 128
#define NROWSBH (BH*SEQ)           // 131072

// ----------------------- scratch (device globals; no runtime alloc) ---------
__device__ float g_n[(size_t)ROWS*DMODEL];
__device__ float g_q[(size_t)ROWS*DMODEL];
__device__ float g_k[(size_t)ROWS*DMODEL];
__device__ float g_v[(size_t)ROWS*DMODEL];
__device__ float g_attn[(size_t)ROWS*DMODEL];
__device__ float g_scores[(size_t)BH*SEQ*SEQ];       // 512MB, reused for cross (BH*SEQ*77)
__device__ float g_rowM[NROWSBH];
__device__ float g_rowInvZ[NROWSBH];
__device__ float g_proj[(size_t)ROWS*2*FFD];
__device__ float g_gg[(size_t)ROWS*FFD];
__device__ float g_stats[8];  // [2i]=min_i,[2i+1]=max_i for i in {q,k,v}; [6]=pmax

// ----------------------- atomic float min/max -------------------------------
__device__ __forceinline__ void atomicMaxF(float* a, float v) {
    if (v >= 0.f) atomicMax((int*)a, __float_as_int(v));
    else          atomicMin((unsigned int*)a, __float_as_uint(v));
}
__device__ __forceinline__ void atomicMinF(float* a, float v) {
    if (v >= 0.f) atomicMin((int*)a, __float_as_int(v));
    else          atomicMax((unsigned int*)a, __float_as_uint(v));
}

// ----------------------- LayerNorm ------------------------------------------
__global__ __launch_bounds__(256) void ln_kernel(
    const float* __restrict__ x, const float* __restrict__ g,
    const float* __restrict__ b, float* __restrict__ o)
{
    const int N = DMODEL;
    size_t row = blockIdx.x;
    const float* xr = x + row * N;
    float* orow = o + row * N;
    int tid = threadIdx.x;

    float lv[5];
    int cnt = 0;
    float s = 0.f;
    for (int i = tid; i < N; i += 256) { float t = xr[i]; lv[cnt++] = t; s += t; }

    __shared__ float sh[8];
    // block sum (mean)
    for (int ofs = 16; ofs; ofs >>= 1) s += __shfl_xor_sync(0xffffffffu, s, ofs);
    if ((tid & 31) == 0) sh[tid >> 5] = s;
    __syncthreads();
    float tot = 0.f;
    #pragma unroll
    for (int i = 0; i < 8; i++) tot += sh[i];
    float mu = tot * (1.f / (float)N);

    float vs = 0.f;
    for (int c = 0; c < cnt; c++) { float d = lv[c] - mu; vs += d * d; }
    __syncthreads();
    for (int ofs = 16; ofs; ofs >>= 1) vs += __shfl_xor_sync(0xffffffffu, vs, ofs);
    if ((tid & 31) == 0) sh[tid >> 5] = vs;
    __syncthreads();
    float vtot = 0.f;
    #pragma unroll
    for (int i = 0; i < 8; i++) vtot += sh[i];
    float inv = rsqrtf(vtot * (1.f / (float)N) + 1e-5f);

    int i = tid;
    for (int c = 0; c < cnt; c++, i += 256)
        orow[i] = (lv[c] - mu) * inv * g[i] + b[i];
}

// ----------------------- SGEMM: C = A[MxK] @ B[KxN] (+bias)(+res) -----------
// N % 128 == 0, K % 8 == 0 required (true for all calls). M arbitrary.
__global__ __launch_bounds__(256) void sgemm_kernel(
    const float* __restrict__ A, const float* __restrict__ B,
    const float* __restrict__ bias, const float* res,
    float* C, int M, int N, int K)
{
    __shared__ float As[8 * 132];
    __shared__ float Bs[8 * 128];
    int tid = threadIdx.x;
    int bx = blockIdx.x, by = blockIdx.y;
    int tx = tid & 15, ty = tid >> 4;
    int aRow = tid >> 1, aCol = (tid & 1) * 4;
    int bRow = tid >> 5, bCol = (tid & 31) * 4;

    float acc[8][8];
    #pragma unroll
    for (int i = 0; i < 8; i++)
        #pragma unroll
        for (int j = 0; j < 8; j++) acc[i][j] = 0.f;

    int gARow = by * 128 + aRow;
    bool aValid = gARow < M;
    const float* aPtr = A + (size_t)gARow * K + aCol;
    const float* bPtr = B + (size_t)bRow * N + (size_t)bx * 128 + bCol;

    for (int k0 = 0; k0 < K; k0 += 8) {
        float4 av = aValid ? *(const float4*)(aPtr + k0) : make_float4(0.f, 0.f, 0.f, 0.f);
        float4 bv = *(const float4*)(bPtr + (size_t)k0 * N);
        As[(aCol + 0) * 132 + aRow] = av.x;
        As[(aCol + 1) * 132 + aRow] = av.y;
        As[(aCol + 2) * 132 + aRow] = av.z;
        As[(aCol + 3) * 132 + aRow] = av.w;
        *(float4*)&Bs[bRow * 128 + bCol] = bv;
        __syncthreads();
        #pragma unroll
        for (int kk = 0; kk < 8; kk++) {
            float4 a0 = *(const float4*)&As[kk * 132 + ty * 8];
            float4 a1 = *(const float4*)&As[kk * 132 + ty * 8 + 4];
            float4 b0 = *(const float4*)&Bs[kk * 128 + tx * 8];
            float4 b1 = *(const float4*)&Bs[kk * 128 + tx * 8 + 4];
            float ar[8] = {a0.x, a0.y, a0.z, a0.w, a1.x, a1.y, a1.z, a1.w};
            float br[8] = {b0.x, b0.y, b0.z, b0.w, b1.x, b1.y, b1.z, b1.w};
            #pragma unroll
            for (int i = 0; i < 8; i++)
                #pragma unroll
                for (int j = 0; j < 8; j++)
                    acc[i][j] += ar[i] * br[j];
        }
        __syncthreads();
    }

    #pragma unroll
    for (int i = 0; i < 8; i++) {
        int row = by * 128 + ty * 8 + i;
        if (row >= M) continue;
        #pragma unroll
        for (int jj = 0; jj < 8; jj += 4) {
            int col = bx * 128 + tx * 8 + jj;
            float4 o;
            o.x = acc[i][jj + 0]; o.y = acc[i][jj + 1];
            o.z = acc[i][jj + 2]; o.w = acc[i][jj + 3];
            if (bias) {
                float4 bb = *(const float4*)(bias + col);
                o.x += bb.x; o.y += bb.y; o.z += bb.z; o.w += bb.w;
            }
            if (res) {
                float4 rv = *(const float4*)(res + (size_t)row * N + col);
                o.x += rv.x; o.y += rv.y; o.z += rv.z; o.w += rv.w;
            }
            *(float4*)(C + (size_t)row * N + col) = o;
        }
    }
}

// ----------------------- stats init / minmax / quant ------------------------
__global__ void init_stats_kernel() {
    int t = threadIdx.x;
    if (t < 3) { g_stats[2 * t] = INFINITY; g_stats[2 * t + 1] = -INFINITY; }
    if (t == 3) g_stats[6] = 0.f;
}

__global__ __launch_bounds__(256) void minmax_kernel(const float* __restrict__ x, size_t n, int slot) {
    float mn = INFINITY, mx = -INFINITY;
    for (size_t i = (size_t)blockIdx.x * blockDim.x + threadIdx.x; i < n;
         i += (size_t)gridDim.x * blockDim.x) {
        float v = x[i];
        mn = fminf(mn, v);
        mx = fmaxf(mx, v);
    }
    __shared__ float smn[8], smx[8];
    int tid = threadIdx.x;
    for (int o = 16; o; o >>= 1) {
        mn = fminf(mn, __shfl_xor_sync(0xffffffffu, mn, o));
        mx = fmaxf(mx, __shfl_xor_sync(0xffffffffu, mx, o));
    }
    if ((tid & 31) == 0) { smn[tid >> 5] = mn; smx[tid >> 5] = mx; }
    __syncthreads();
    if (tid == 0) {
        for (int i = 1; i < 8; i++) { mn = fminf(mn, smn[i]); mx = fmaxf(mx, smx[i]); }
        atomicMinF(&g_stats[2 * slot], mn);
        atomicMaxF(&g_stats[2 * slot + 1], mx);
    }
}

__global__ __launch_bounds__(256) void quant_kernel(float* x, size_t n, int slot) {
    float mn = g_stats[2 * slot], mx = g_stats[2 * slot + 1];
    float delta = (mx - mn) * (1.f / 255.f);
    float zp = rintf(-mn / delta);
    for (size_t i = (size_t)blockIdx.x * blockDim.x + threadIdx.x; i < n;
         i += (size_t)gridDim.x * blockDim.x) {
        float q = rintf(x[i] / delta) + zp;
        q = fminf(fmaxf(q, 0.f), 255.f);
        x[i] = (q - zp) * delta;
    }
}

// ----------------------- scores = scale * Q @ K^T (batched over B*H) --------
// Q rows per batch = SEQ, K rows per batch = SK. Head stride HDIM within DMODEL.
__global__ __launch_bounds__(256) void scores_kernel(
    const float* __restrict__ q, const float* __restrict__ kt, int SK, float scale)
{
    int bh = blockIdx.z, b = bh >> 4, h = bh & 15;
    const float* qb = q + ((size_t)b * SEQ) * DMODEL + h * HDIM;
    const float* kb = kt + ((size_t)b * SK) * DMODEL + h * HDIM;
    __shared__ float qs[72 * 68];
    __shared__ float ks[72 * 68];
    int tid = threadIdx.x;
    int qrow0 = blockIdx.y * 64, kcol0 = blockIdx.x * 64;

    for (int idx = tid; idx < 64 * 72; idx += 256) {
        int r = idx / 72, kk = idx % 72;
        qs[kk * 68 + r] = qb[(size_t)(qrow0 + r) * DMODEL + kk];
        int kr = kcol0 + r;
        ks[kk * 68 + r] = (kr < SK) ? kb[(size_t)kr * DMODEL + kk] : 0.f;
    }
    __syncthreads();

    int tx = tid & 15, ty = tid >> 4;
    float acc[4][4];
    #pragma unroll
    for (int i = 0; i < 4; i++)
        #pragma unroll
        for (int j = 0; j < 4; j++) acc[i][j] = 0.f;

    #pragma unroll 4
    for (int kk = 0; kk < 72; kk++) {
        float4 qv = *(const float4*)&qs[kk * 68 + ty * 4];
        float4 kv = *(const float4*)&ks[kk * 68 + tx * 4];
        float qa[4] = {qv.x, qv.y, qv.z, qv.w};
        float ka[4] = {kv.x, kv.y, kv.z, kv.w};
        #pragma unroll
        for (int i = 0; i < 4; i++)
            #pragma unroll
            for (int j = 0; j < 4; j++)
                acc[i][j] += qa[i] * ka[j];
    }

    #pragma unroll
    for (int i = 0; i < 4; i++) {
        int row = qrow0 + ty * 4 + i;
        size_t base = ((size_t)bh * SEQ + row) * SK;
        #pragma unroll
        for (int j = 0; j < 4; j++) {
            int col = kcol0 + tx * 4 + j;
            if (col < SK) g_scores[base + col] = acc[i][j] * scale;
        }
    }
}

// ----------------------- per-row softmax stats ------------------------------
__global__ __launch_bounds__(128) void softmax_stats_kernel(int SK) {
    size_t row = blockIdx.x;
    const float* sr = g_scores + row * (size_t)SK;
    int tid = threadIdx.x;
    float vals[8];
    int cnt = 0;
    float m = -INFINITY;
    for (int i = tid; i < SK; i += 128) { float t = sr[i]; vals[cnt++] = t; m = fmaxf(m, t); }
    __shared__ float sh[4];
    for (int o = 16; o; o >>= 1) m = fmaxf(m, __shfl_xor_sync(0xffffffffu, m, o));
    if ((tid & 31) == 0) sh[tid >> 5] = m;
    __syncthreads();
    m = fmaxf(fmaxf(sh[0], sh[1]), fmaxf(sh[2], sh[3]));
    float z = 0.f;
    for (int c = 0; c < cnt; c++) z += expf(vals[c] - m);
    __syncthreads();
    for (int o = 16; o; o >>= 1) z += __shfl_xor_sync(0xffffffffu, z, o);
    __shared__ float sh2[4];
    if ((tid & 31) == 0) sh2[tid >> 5] = z;
    __syncthreads();
    if (tid == 0) {
        z = sh2[0] + sh2[1] + sh2[2] + sh2[3];
        g_rowM[row] = m;
        g_rowInvZ[row] = 1.f / z;
    }
}

__global__ __launch_bounds__(256) void maxinv_kernel() {
    float m = 0.f;
    for (int i = blockIdx.x * blockDim.x + threadIdx.x; i < NROWSBH;
         i += gridDim.x * blockDim.x)
        m = fmaxf(m, g_rowInvZ[i]);
    __shared__ float sh[8];
    int tid = threadIdx.x;
    for (int o = 16; o; o >>= 1) m = fmaxf(m, __shfl_xor_sync(0xffffffffu, m, o));
    if ((tid & 31) == 0) sh[tid >> 5] = m;
    __syncthreads();
    if (tid == 0) {
        for (int i = 1; i < 8; i++) m = fmaxf(m, sh[i]);
        atomicMaxF(&g_stats[6], m);
    }
}

// ----------------------- out = quantprobs @ V (fused transform) -------------
// Block: 128 q-rows x all 72 head cols; blockIdx.y = bh.
__global__ __launch_bounds__(256) void pv_kernel(const float* __restrict__ v, int SK) {
    int bh = blockIdx.y, b = bh >> 4, h = bh & 15;
    int m0 = blockIdx.x * 128;
    size_t rowbase = (size_t)bh * SEQ + m0;
    const float* vb = v + ((size_t)b * SK) * DMODEL + h * HDIM;

    float pmax = g_stats[6];
    float dp = pmax * (1.f / 255.f);
    float idp = 255.f / pmax;

    __shared__ float ps[32 * 132];
    __shared__ float vs[32 * 72];
    int tid = threadIdx.x;
    int tx = tid & 7, ty = tid >> 3;   // tx: 8 col-groups of 9, ty: 32 row-groups of 4

    float acc[4][9];
    #pragma unroll
    for (int i = 0; i < 4; i++)
        #pragma unroll
        for (int j = 0; j < 9; j++) acc[i][j] = 0.f;

    for (int k0 = 0; k0 < SK; k0 += 32) {
        for (int idx = tid; idx < 128 * 32; idx += 256) {
            int r = idx >> 5, kk = idx & 31;
            int kg = k0 + kk;
            float pq = 0.f;
            if (kg < SK) {
                size_t grow = rowbase + r;
                float s = g_scores[grow * SK + kg];
                float p = expf(s - g_rowM[grow]) * g_rowInvZ[grow];
                pq = fminf(rintf(p * idp), 255.f) * dp;
            }
            ps[kk * 132 + r] = pq;
        }
        for (int idx = tid; idx < 32 * 72; idx += 256) {
            int kk = idx / 72, c = idx % 72;
            int kg = k0 + kk;
            vs[idx] = (kg < SK) ? vb[(size_t)kg * DMODEL + c] : 0.f;
        }
        __syncthreads();
        #pragma unroll 4
        for (int kk = 0; kk < 32; kk++) {
            float4 p4 = *(const float4*)&ps[kk * 132 + ty * 4];
            float pr[4] = {p4.x, p4.y, p4.z, p4.w};
            #pragma unroll
            for (int j = 0; j < 9; j++) {
                float vv = vs[kk * 72 + tx * 9 + j];
                #pragma unroll
                for (int i = 0; i < 4; i++) acc[i][j] += pr[i] * vv;
            }
        }
        __syncthreads();
    }

    #pragma unroll
    for (int i = 0; i < 4; i++) {
        int row = m0 + ty * 4 + i;
        size_t base = ((size_t)b * SEQ + row) * DMODEL + h * HDIM + tx * 9;
        #pragma unroll
        for (int j = 0; j < 9; j++) g_attn[base + j] = acc[i][j];
    }
}

// ----------------------- GEGLU ----------------------------------------------
__global__ __launch_bounds__(256) void geglu_kernel() {
    size_t n = (size_t)ROWS * FFD;
    for (size_t idx = (size_t)blockIdx.x * blockDim.x + threadIdx.x; idx < n;
         idx += (size_t)gridDim.x * blockDim.x) {
        size_t row = idx / FFD;
        int c = (int)(idx % FFD);
        float a  = g_proj[row * (2 * FFD) + c];
        float gt = g_proj[row * (2 * FFD) + FFD + c];
        float gl = 0.5f * gt * (1.f + erff(gt * 0.70710678118654752440f));
        g_gg[idx] = a * gl;
    }
}

// ----------------------- host orchestration ---------------------------------
static inline void launch_gemm(const float* A, const float* B, const float* bias,
                               const float* res, float* C, int M, int N, int K) {
    dim3 grid(N / 128, (M + 127) / 128);
    sgemm_kernel<<<grid, 256>>>(A, B, bias, res, C, M, N, K);
}

extern "C" void kernel_launch(void* const* d_in, const int* in_sizes, int n_in,
                              void* d_out, int out_size) {
    (void)in_sizes; (void)n_in; (void)out_size;
    const float* hs    = (const float*)d_in[0];
    const float* enc   = (const float*)d_in[1];
    const float* ln1g  = (const float*)d_in[2];
    const float* ln1b  = (const float*)d_in[3];
    const float* Wq1   = (const float*)d_in[4];
    const float* Wk1   = (const float*)d_in[5];
    const float* Wv1   = (const float*)d_in[6];
    const float* Wo1   = (const float*)d_in[7];
    const float* bo1   = (const float*)d_in[8];
    const float* ln2g  = (const float*)d_in[9];
    const float* ln2b  = (const float*)d_in[10];
    const float* Wq2   = (const float*)d_in[11];
    const float* Wk2   = (const float*)d_in[12];
    const float* Wv2   = (const float*)d_in[13];
    const float* Wo2   = (const float*)d_in[14];
    const float* bo2   = (const float*)d_in[15];
    const float* ln3g  = (const float*)d_in[16];
    const float* ln3b  = (const float*)d_in[17];
    const float* Wff1  = (const float*)d_in[18];
    const float* bff1  = (const float*)d_in[19];
    const float* Wff2  = (const float*)d_in[20];
    const float* bff2  = (const float*)d_in[21];
    float* out = (float*)d_out;

    void* p;
    cudaGetSymbolAddress(&p, g_n);    float* n_   = (float*)p;
    cudaGetSymbolAddress(&p, g_q);    float* q_   = (float*)p;
    cudaGetSymbolAddress(&p, g_k);    float* k_   = (float*)p;
    cudaGetSymbolAddress(&p, g_v);    float* v_   = (float*)p;
    cudaGetSymbolAddress(&p, g_attn); float* at_  = (float*)p;
    cudaGetSymbolAddress(&p, g_proj); float* pj_  = (float*)p;
    cudaGetSymbolAddress(&p, g_gg);   float* gg_  = (float*)p;

    const float scale = 1.0f / sqrtf((float)HDIM);
    const size_t nQ = (size_t)ROWS * DMODEL;
    const size_t nE = (size_t)ENCROWS * DMODEL;

    // ================= self-attention =================
    ln_kernel<<<ROWS, 256>>>(hs, ln1g, ln1b, n_);
    launch_gemm(n_, Wq1, nullptr, nullptr, q_, ROWS, DMODEL, DMODEL);
    launch_gemm(n_, Wk1, nullptr, nullptr, k_, ROWS, DMODEL, DMODEL);
    launch_gemm(n_, Wv1, nullptr, nullptr, v_, ROWS, DMODEL, DMODEL);
    init_stats_kernel<<<1, 32>>>();
    minmax_kernel<<<512, 256>>>(q_, nQ, 0);
    minmax_kernel<<<512, 256>>>(k_, nQ, 1);
    minmax_kernel<<<512, 256>>>(v_, nQ, 2);
    quant_kernel<<<2048, 256>>>(q_, nQ, 0);
    quant_kernel<<<2048, 256>>>(k_, nQ, 1);
    quant_kernel<<<2048, 256>>>(v_, nQ, 2);
    scores_kernel<<<dim3(SEQ / 64, SEQ / 64, BH), 256>>>(q_, k_, SEQ, scale);
    softmax_stats_kernel<<<NROWSBH, 128>>>(SEQ);
    maxinv_kernel<<<64, 256>>>();
    pv_kernel<<<dim3(SEQ / 128, BH), 256>>>(v_, SEQ);
    launch_gemm(at_, Wo1, bo1, hs, out, ROWS, DMODEL, DMODEL);

    // ================= cross-attention =================
    ln_kernel<<<ROWS, 256>>>(out, ln2g, ln2b, n_);
    launch_gemm(n_, Wq2, nullptr, nullptr, q_, ROWS, DMODEL, DMODEL);
    launch_gemm(enc, Wk2, nullptr, nullptr, k_, ENCROWS, DMODEL, DMODEL);
    launch_gemm(enc, Wv2, nullptr, nullptr, v_, ENCROWS, DMODEL, DMODEL);
    init_stats_kernel<<<1, 32>>>();
    minmax_kernel<<<512, 256>>>(q_, nQ, 0);
    minmax_kernel<<<512, 256>>>(k_, nE, 1);
    minmax_kernel<<<512, 256>>>(v_, nE, 2);
    quant_kernel<<<2048, 256>>>(q_, nQ, 0);
    quant_kernel<<<512, 256>>>(k_, nE, 1);
    quant_kernel<<<512, 256>>>(v_, nE, 2);
    scores_kernel<<<dim3((SENC + 63) / 64, SEQ / 64, BH), 256>>>(q_, k_, SENC, scale);
    softmax_stats_kernel<<<NROWSBH, 128>>>(SENC);
    maxinv_kernel<<<64, 256>>>();
    pv_kernel<<<dim3(SEQ / 128, BH), 256>>>(v_, SENC);
    launch_gemm(at_, Wo2, bo2, out, out, ROWS, DMODEL, DMODEL);

    // ================= feed-forward (GEGLU) =================
    ln_kernel<<<ROWS, 256>>>(out, ln3g, ln3b, n_);
    launch_gemm(n_, Wff1, bff1, nullptr, pj_, ROWS, 2 * FFD, DMODEL);
    geglu_kernel<<<8192, 256>>>();
    launch_gemm(gg_, Wff2, bff2, out, out, ROWS, DMODEL, FFD);
}

// round 4
// speedup vs baseline: 1.8238x; 1.8238x over previous
#include <cuda_runtime.h>
#include <cuda_bf16.h>
#include <math.h>
#include <stdint.h>

// Problem dims
#define BATCH   8
#define SEQ     1024
#define DMODEL  1152
#define NHEAD   16
#define HDIM    72
#define SENC    77
#define FFD     4608
#define ROWS    (BATCH*SEQ)        // 8192
#define ENCROWS (BATCH*SENC)       // 616
#define BH      (BATCH*NHEAD)      // 128
#define NROWSBH (BH*SEQ)           // 131072

__device__ __forceinline__ uint32_t smem_to_u32(const void* smem_ptr) {
    uint32_t addr;
    asm("{ .reg .u64 tmp; cvta.to.shared.u64 tmp, %1; cvt.u32.u64 %0, tmp; }"
        : "=r"(addr) : "l"(smem_ptr));
    return addr;
}

// ----------------------- scratch (device globals; no runtime alloc) ---------
__device__ float g_n[(size_t)ROWS*DMODEL];
__device__ float g_q[(size_t)ROWS*DMODEL];
__device__ float g_k[(size_t)ROWS*DMODEL];
__device__ float g_v[(size_t)ROWS*DMODEL];
__device__ float g_attn[(size_t)ROWS*DMODEL];
__device__ float g_scores[(size_t)BH*SEQ*SEQ];       // 512MB, reused for cross
__device__ float g_rowM[NROWSBH];
__device__ float g_rowInvZ[NROWSBH];
__device__ float g_proj[(size_t)ROWS*2*FFD];
__device__ float g_gg[(size_t)ROWS*FFD];
__device__ float g_stats[8];
// bf16 hi/lo operand buffers
__device__ __nv_bfloat16 g_ah[(size_t)ROWS*FFD];     // max M*K = 8192*4608
__device__ __nv_bfloat16 g_al[(size_t)ROWS*FFD];
__device__ __nv_bfloat16 g_bh[(size_t)(2*FFD)*DMODEL]; // max N*K = 9216*1152
__device__ __nv_bfloat16 g_bl[(size_t)(2*FFD)*DMODEL];

// ----------------------- atomic float min/max -------------------------------
__device__ __forceinline__ void atomicMaxF(float* a, float v) {
    if (v >= 0.f) atomicMax((int*)a, __float_as_int(v));
    else          atomicMin((unsigned int*)a, __float_as_uint(v));
}
__device__ __forceinline__ void atomicMinF(float* a, float v) {
    if (v >= 0.f) atomicMin((int*)a, __float_as_int(v));
    else          atomicMax((unsigned int*)a, __float_as_uint(v));
}

// ----------------------- LayerNorm ------------------------------------------
__global__ __launch_bounds__(256) void ln_kernel(
    const float* __restrict__ x, const float* __restrict__ g,
    const float* __restrict__ b, float* __restrict__ o)
{
    const int N = DMODEL;
    size_t row = blockIdx.x;
    const float* xr = x + row * N;
    float* orow = o + row * N;
    int tid = threadIdx.x;

    float lv[5];
    int cnt = 0;
    float s = 0.f;
    for (int i = tid; i < N; i += 256) { float t = xr[i]; lv[cnt++] = t; s += t; }

    __shared__ float sh[8];
    for (int ofs = 16; ofs; ofs >>= 1) s += __shfl_xor_sync(0xffffffffu, s, ofs);
    if ((tid & 31) == 0) sh[tid >> 5] = s;
    __syncthreads();
    float tot = 0.f;
    #pragma unroll
    for (int i = 0; i < 8; i++) tot += sh[i];
    float mu = tot * (1.f / (float)N);

    float vs = 0.f;
    for (int c = 0; c < cnt; c++) { float d = lv[c] - mu; vs += d * d; }
    __syncthreads();
    for (int ofs = 16; ofs; ofs >>= 1) vs += __shfl_xor_sync(0xffffffffu, vs, ofs);
    if ((tid & 31) == 0) sh[tid >> 5] = vs;
    __syncthreads();
    float vtot = 0.f;
    #pragma unroll
    for (int i = 0; i < 8; i++) vtot += sh[i];
    float inv = rsqrtf(vtot * (1.f / (float)N) + 1e-5f);

    int i = tid;
    for (int c = 0; c < cnt; c++, i += 256)
        orow[i] = (lv[c] - mu) * inv * g[i] + b[i];
}

// ----------------------- fp32 -> bf16 hi/lo split ----------------------------
__global__ __launch_bounds__(256) void convert_split_kernel(
    const float* __restrict__ x, size_t n4,
    __nv_bfloat16* __restrict__ h, __nv_bfloat16* __restrict__ l)
{
    for (size_t i = (size_t)blockIdx.x * blockDim.x + threadIdx.x; i < n4;
         i += (size_t)gridDim.x * blockDim.x) {
        float4 v = ((const float4*)x)[i];
        __nv_bfloat16 h0 = __float2bfloat16(v.x);
        __nv_bfloat16 h1 = __float2bfloat16(v.y);
        __nv_bfloat16 h2 = __float2bfloat16(v.z);
        __nv_bfloat16 h3 = __float2bfloat16(v.w);
        __nv_bfloat162* hp = (__nv_bfloat162*)h;
        __nv_bfloat162* lp = (__nv_bfloat162*)l;
        hp[2*i]   = __nv_bfloat162(h0, h1);
        hp[2*i+1] = __nv_bfloat162(h2, h3);
        lp[2*i]   = __nv_bfloat162(__float2bfloat16(v.x - __bfloat162float(h0)),
                                   __float2bfloat16(v.y - __bfloat162float(h1)));
        lp[2*i+1] = __nv_bfloat162(__float2bfloat16(v.z - __bfloat162float(h2)),
                                   __float2bfloat16(v.w - __bfloat162float(h3)));
    }
}

// ----------------------- weight transpose + hi/lo split ----------------------
// W: [K][N] fp32 row-major -> Th/Tl: [N][K] bf16
__global__ __launch_bounds__(256) void wt_trans_split_kernel(
    const float* __restrict__ W, int K, int N,
    __nv_bfloat16* __restrict__ Th, __nv_bfloat16* __restrict__ Tl)
{
    __shared__ float tile[32][33];
    int n0 = blockIdx.x * 32, k0 = blockIdx.y * 32;
    int tx = threadIdx.x & 31, ty = threadIdx.x >> 5;
    #pragma unroll
    for (int r = ty; r < 32; r += 8) {
        int k = k0 + r, n = n0 + tx;
        tile[r][tx] = (k < K && n < N) ? W[(size_t)k * N + n] : 0.f;
    }
    __syncthreads();
    #pragma unroll
    for (int r = ty; r < 32; r += 8) {
        int n = n0 + r, k = k0 + tx;
        if (n < N && k < K) {
            float x = tile[tx][r];
            __nv_bfloat16 hh = __float2bfloat16(x);
            Th[(size_t)n * K + k] = hh;
            Tl[(size_t)n * K + k] = __float2bfloat16(x - __bfloat162float(hh));
        }
    }
}

// ----------------------- mma.sync bf16x3 GEMM -------------------------------
// C[M,N] = (Ah+Al)[M,K] @ (Bh+Bl)[N,K]^T (+bias)(+res), fp32 accumulate.
// CTA tile 128x128x32, 256 threads = 8 warps (4M x 2N), warp tile 32x64.
// smem: per stage, 4 tiles of 128 rows x 80B (32 bf16 used) = 40960B; 2 stages.
#define TC_STAGE_BYTES 40960
#define TC_SMEM_TOTAL  (2*TC_STAGE_BYTES)

__device__ __forceinline__ void cp16(uint32_t dst, const void* src, uint32_t sz) {
    asm volatile("cp.async.cg.shared.global [%0], [%1], 16, %2;"
                 :: "r"(dst), "l"(src), "r"(sz) : "memory");
}
template<int NN> __device__ __forceinline__ void cpasync_wait() {
    asm volatile("cp.async.wait_group %0;" :: "n"(NN) : "memory");
}
__device__ __forceinline__ void ldsm_x4(uint32_t* r, uint32_t addr) {
    asm volatile("ldmatrix.sync.aligned.m8n8.x4.shared.b16 {%0,%1,%2,%3}, [%4];"
        : "=r"(r[0]), "=r"(r[1]), "=r"(r[2]), "=r"(r[3]) : "r"(addr));
}
__device__ __forceinline__ void mma_bf16(float* c, const uint32_t* a, const uint32_t* b) {
    asm volatile("mma.sync.aligned.m16n8k16.row.col.f32.bf16.bf16.f32 "
        "{%0,%1,%2,%3}, {%4,%5,%6,%7}, {%8,%9}, {%0,%1,%2,%3};"
        : "+f"(c[0]), "+f"(c[1]), "+f"(c[2]), "+f"(c[3])
        : "r"(a[0]), "r"(a[1]), "r"(a[2]), "r"(a[3]), "r"(b[0]), "r"(b[1]));
}

__device__ __forceinline__ void tc_load_stage(
    uint32_t sbase,
    const __nv_bfloat16* __restrict__ Ah, const __nv_bfloat16* __restrict__ Al,
    const __nv_bfloat16* __restrict__ Bh, const __nv_bfloat16* __restrict__ Bl,
    int m0, int M, int n0, int K, int k0, int tid)
{
    #pragma unroll
    for (int i = 0; i < 2; i++) {
        int c = tid + i * 256;
        int row = c >> 2, kc = c & 3;
        uint32_t soff = (uint32_t)(row * 80 + kc * 16);
        size_t goffA = (size_t)(m0 + row) * K + k0 + kc * 8;
        uint32_t szA = ((m0 + row) < M) ? 16u : 0u;
        cp16(sbase + soff,         Ah + goffA, szA);
        cp16(sbase + 10240 + soff, Al + goffA, szA);
        size_t goffB = (size_t)(n0 + row) * K + k0 + kc * 8;
        cp16(sbase + 20480 + soff, Bh + goffB, 16u);
        cp16(sbase + 30720 + soff, Bl + goffB, 16u);
    }
    asm volatile("cp.async.commit_group;" ::: "memory");
}

__global__ __launch_bounds__(256) void tc_gemm_kernel(
    const __nv_bfloat16* __restrict__ Ah, const __nv_bfloat16* __restrict__ Al,
    const __nv_bfloat16* __restrict__ Bh, const __nv_bfloat16* __restrict__ Bl,
    const float* __restrict__ bias, const float* __restrict__ res,
    float* __restrict__ C, int M, int N, int K)
{
    extern __shared__ char smem[];
    uint32_t sb = smem_to_u32(smem);
    int tid = threadIdx.x;
    int wid = tid >> 5, lane = tid & 31;
    int n0 = blockIdx.x * 128, m0 = blockIdx.y * 128;
    int wm = wid & 3, wn = wid >> 2;

    float acc[2][8][4];
    #pragma unroll
    for (int mt = 0; mt < 2; mt++)
        #pragma unroll
        for (int nt = 0; nt < 8; nt++)
            #pragma unroll
            for (int e = 0; e < 4; e++) acc[mt][nt][e] = 0.f;

    const int KT = K >> 5;    // k-tiles of 32

    tc_load_stage(sb, Ah, Al, Bh, Bl, m0, M, n0, K, 0, tid);

    for (int t = 0; t < KT; t++) {
        if (t + 1 < KT) {
            tc_load_stage(sb + ((t + 1) & 1) * TC_STAGE_BYTES,
                          Ah, Al, Bh, Bl, m0, M, n0, K, (t + 1) << 5, tid);
            cpasync_wait<1>();
        } else {
            cpasync_wait<0>();
        }
        __syncthreads();

        uint32_t base = sb + (t & 1) * TC_STAGE_BYTES;
        #pragma unroll
        for (int kk = 0; kk < 2; kk++) {
            uint32_t ah[2][4], al[2][4];
            #pragma unroll
            for (int mt = 0; mt < 2; mt++) {
                uint32_t arow = (uint32_t)(wm * 32 + mt * 16 + (lane & 15));
                uint32_t abyte = arow * 80 + kk * 32 + ((lane >> 4) << 4);
                ldsm_x4(ah[mt], base + abyte);
                ldsm_x4(al[mt], base + 10240 + abyte);
            }
            #pragma unroll
            for (int bp = 0; bp < 4; bp++) {
                // B tile smem is [n][k] (k-contiguous) == col-major for row.col mma:
                // NON-trans ldmatrix, same as A. 4 matrices: (n0-7,k0-7),(n0-7,k8-15),
                // (n8-15,k0-7),(n8-15,k8-15) -> reg pairs {0,1} and {2,3}.
                uint32_t brow = (uint32_t)(wn * 64 + bp * 16 + (lane & 7) + (((lane >> 4) & 1) << 3));
                uint32_t bbyte = brow * 80 + kk * 32 + (((lane >> 3) & 1) << 4);
                uint32_t bh4[4], bl4[4];
                ldsm_x4(bh4, base + 20480 + bbyte);
                ldsm_x4(bl4, base + 30720 + bbyte);
                #pragma unroll
                for (int sub = 0; sub < 2; sub++) {
                    int nt = bp * 2 + sub;
                    #pragma unroll
                    for (int mt = 0; mt < 2; mt++) {
                        mma_bf16(acc[mt][nt], ah[mt], bh4 + sub * 2);
                        mma_bf16(acc[mt][nt], ah[mt], bl4 + sub * 2);
                        mma_bf16(acc[mt][nt], al[mt], bh4 + sub * 2);
                    }
                }
            }
        }
        __syncthreads();
    }

    // epilogue
    #pragma unroll
    for (int mt = 0; mt < 2; mt++) {
        int r0 = m0 + wm * 32 + mt * 16 + (lane >> 2);
        #pragma unroll
        for (int nt = 0; nt < 8; nt++) {
            int cc = n0 + wn * 64 + nt * 8 + (lane & 3) * 2;
            #pragma unroll
            for (int h = 0; h < 2; h++) {
                int r = r0 + h * 8;
                if (r >= M) continue;
                float2 o = make_float2(acc[mt][nt][h * 2], acc[mt][nt][h * 2 + 1]);
                if (bias) {
                    float2 bb = *(const float2*)(bias + cc);
                    o.x += bb.x; o.y += bb.y;
                }
                if (res) {
                    float2 rv = *(const float2*)(res + (size_t)r * N + cc);
                    o.x += rv.x; o.y += rv.y;
                }
                *(float2*)(C + (size_t)r * N + cc) = o;
            }
        }
    }
}

// ----------------------- stats init / minmax / quant ------------------------
__global__ void init_stats_kernel() {
    int t = threadIdx.x;
    if (t < 3) { g_stats[2 * t] = INFINITY; g_stats[2 * t + 1] = -INFINITY; }
    if (t == 3) g_stats[6] = 0.f;
}

__global__ __launch_bounds__(256) void minmax_kernel(const float* __restrict__ x, size_t n, int slot) {
    float mn = INFINITY, mx = -INFINITY;
    for (size_t i = (size_t)blockIdx.x * blockDim.x + threadIdx.x; i < n;
         i += (size_t)gridDim.x * blockDim.x) {
        float v = x[i];
        mn = fminf(mn, v);
        mx = fmaxf(mx, v);
    }
    __shared__ float smn[8], smx[8];
    int tid = threadIdx.x;
    for (int o = 16; o; o >>= 1) {
        mn = fminf(mn, __shfl_xor_sync(0xffffffffu, mn, o));
        mx = fmaxf(mx, __shfl_xor_sync(0xffffffffu, mx, o));
    }
    if ((tid & 31) == 0) { smn[tid >> 5] = mn; smx[tid >> 5] = mx; }
    __syncthreads();
    if (tid == 0) {
        for (int i = 1; i < 8; i++) { mn = fminf(mn, smn[i]); mx = fmaxf(mx, smx[i]); }
        atomicMinF(&g_stats[2 * slot], mn);
        atomicMaxF(&g_stats[2 * slot + 1], mx);
    }
}

__global__ __launch_bounds__(256) void quant_kernel(float* x, size_t n, int slot) {
    float mn = g_stats[2 * slot], mx = g_stats[2 * slot + 1];
    float delta = (mx - mn) * (1.f / 255.f);
    float zp = rintf(-mn / delta);
    for (size_t i = (size_t)blockIdx.x * blockDim.x + threadIdx.x; i < n;
         i += (size_t)gridDim.x * blockDim.x) {
        float q = rintf(x[i] / delta) + zp;
        q = fminf(fmaxf(q, 0.f), 255.f);
        x[i] = (q - zp) * delta;
    }
}

// ----------------------- scores = scale * Q @ K^T (batched over B*H) --------
__global__ __launch_bounds__(256) void scores_kernel(
    const float* __restrict__ q, const float* __restrict__ kt, int SK, float scale)
{
    int bh = blockIdx.z, b = bh >> 4, h = bh & 15;
    const float* qb = q + ((size_t)b * SEQ) * DMODEL + h * HDIM;
    const float* kb = kt + ((size_t)b * SK) * DMODEL + h * HDIM;
    __shared__ float qs[72 * 68];
    __shared__ float ks[72 * 68];
    int tid = threadIdx.x;
    int qrow0 = blockIdx.y * 64, kcol0 = blockIdx.x * 64;

    for (int idx = tid; idx < 64 * 72; idx += 256) {
        int r = idx / 72, kk = idx % 72;
        qs[kk * 68 + r] = qb[(size_t)(qrow0 + r) * DMODEL + kk];
        int kr = kcol0 + r;
        ks[kk * 68 + r] = (kr < SK) ? kb[(size_t)kr * DMODEL + kk] : 0.f;
    }
    __syncthreads();

    int tx = tid & 15, ty = tid >> 4;
    float acc[4][4];
    #pragma unroll
    for (int i = 0; i < 4; i++)
        #pragma unroll
        for (int j = 0; j < 4; j++) acc[i][j] = 0.f;

    #pragma unroll 4
    for (int kk = 0; kk < 72; kk++) {
        float4 qv = *(const float4*)&qs[kk * 68 + ty * 4];
        float4 kv = *(const float4*)&ks[kk * 68 + tx * 4];
        float qa[4] = {qv.x, qv.y, qv.z, qv.w};
        float ka[4] = {kv.x, kv.y, kv.z, kv.w};
        #pragma unroll
        for (int i = 0; i < 4; i++)
            #pragma unroll
            for (int j = 0; j < 4; j++)
                acc[i][j] += qa[i] * ka[j];
    }

    #pragma unroll
    for (int i = 0; i < 4; i++) {
        int row = qrow0 + ty * 4 + i;
        size_t base = ((size_t)bh * SEQ + row) * SK;
        #pragma unroll
        for (int j = 0; j < 4; j++) {
            int col = kcol0 + tx * 4 + j;
            if (col < SK) g_scores[base + col] = acc[i][j] * scale;
        }
    }
}

// ----------------------- per-row softmax stats ------------------------------
__global__ __launch_bounds__(128) void softmax_stats_kernel(int SK) {
    size_t row = blockIdx.x;
    const float* sr = g_scores + row * (size_t)SK;
    int tid = threadIdx.x;
    float vals[8];
    int cnt = 0;
    float m = -INFINITY;
    for (int i = tid; i < SK; i += 128) { float t = sr[i]; vals[cnt++] = t; m = fmaxf(m, t); }
    __shared__ float sh[4];
    for (int o = 16; o; o >>= 1) m = fmaxf(m, __shfl_xor_sync(0xffffffffu, m, o));
    if ((tid & 31) == 0) sh[tid >> 5] = m;
    __syncthreads();
    m = fmaxf(fmaxf(sh[0], sh[1]), fmaxf(sh[2], sh[3]));
    float z = 0.f;
    for (int c = 0; c < cnt; c++) z += expf(vals[c] - m);
    __syncthreads();
    for (int o = 16; o; o >>= 1) z += __shfl_xor_sync(0xffffffffu, z, o);
    __shared__ float sh2[4];
    if ((tid & 31) == 0) sh2[tid >> 5] = z;
    __syncthreads();
    if (tid == 0) {
        z = sh2[0] + sh2[1] + sh2[2] + sh2[3];
        g_rowM[row] = m;
        g_rowInvZ[row] = 1.f / z;
    }
}

__global__ __launch_bounds__(256) void maxinv_kernel() {
    float m = 0.f;
    for (int i = blockIdx.x * blockDim.x + threadIdx.x; i < NROWSBH;
         i += gridDim.x * blockDim.x)
        m = fmaxf(m, g_rowInvZ[i]);
    __shared__ float sh[8];
    int tid = threadIdx.x;
    for (int o = 16; o; o >>= 1) m = fmaxf(m, __shfl_xor_sync(0xffffffffu, m, o));
    if ((tid & 31) == 0) sh[tid >> 5] = m;
    __syncthreads();
    if (tid == 0) {
        for (int i = 1; i < 8; i++) m = fmaxf(m, sh[i]);
        atomicMaxF(&g_stats[6], m);
    }
}

// ----------------------- out = quantprobs @ V (fused transform) -------------
__global__ __launch_bounds__(256) void pv_kernel(const float* __restrict__ v, int SK) {
    int bh = blockIdx.y, b = bh >> 4, h = bh & 15;
    int m0 = blockIdx.x * 128;
    size_t rowbase = (size_t)bh * SEQ + m0;
    const float* vb = v + ((size_t)b * SK) * DMODEL + h * HDIM;

    float pmax = g_stats[6];
    float dp = pmax * (1.f / 255.f);
    float idp = 255.f / pmax;

    __shared__ float ps[32 * 132];
    __shared__ float vs[32 * 72];
    int tid = threadIdx.x;
    int tx = tid & 7, ty = tid >> 3;

    float acc[4][9];
    #pragma unroll
    for (int i = 0; i < 4; i++)
        #pragma unroll
        for (int j = 0; j < 9; j++) acc[i][j] = 0.f;

    for (int k0 = 0; k0 < SK; k0 += 32) {
        for (int idx = tid; idx < 128 * 32; idx += 256) {
            int r = idx >> 5, kk = idx & 31;
            int kg = k0 + kk;
            float pq = 0.f;
            if (kg < SK) {
                size_t grow = rowbase + r;
                float s = g_scores[grow * SK + kg];
                float p = expf(s - g_rowM[grow]) * g_rowInvZ[grow];
                pq = fminf(rintf(p * idp), 255.f) * dp;
            }
            ps[kk * 132 + r] = pq;
        }
        for (int idx = tid; idx < 32 * 72; idx += 256) {
            int kk = idx / 72, c = idx % 72;
            int kg = k0 + kk;
            vs[idx] = (kg < SK) ? vb[(size_t)kg * DMODEL + c] : 0.f;
        }
        __syncthreads();
        #pragma unroll 4
        for (int kk = 0; kk < 32; kk++) {
            float4 p4 = *(const float4*)&ps[kk * 132 + ty * 4];
            float pr[4] = {p4.x, p4.y, p4.z, p4.w};
            #pragma unroll
            for (int j = 0; j < 9; j++) {
                float vv = vs[kk * 72 + tx * 9 + j];
                #pragma unroll
                for (int i = 0; i < 4; i++) acc[i][j] += pr[i] * vv;
            }
        }
        __syncthreads();
    }

    #pragma unroll
    for (int i = 0; i < 4; i++) {
        int row = m0 + ty * 4 + i;
        size_t base = ((size_t)b * SEQ + row) * DMODEL + h * HDIM + tx * 9;
        #pragma unroll
        for (int j = 0; j < 9; j++) g_attn[base + j] = acc[i][j];
    }
}

// ----------------------- GEGLU ----------------------------------------------
__global__ __launch_bounds__(256) void geglu_kernel() {
    size_t n = (size_t)ROWS * FFD;
    for (size_t idx = (size_t)blockIdx.x * blockDim.x + threadIdx.x; idx < n;
         idx += (size_t)gridDim.x * blockDim.x) {
        size_t row = idx / FFD;
        int c = (int)(idx % FFD);
        float a  = g_proj[row * (2 * FFD) + c];
        float gt = g_proj[row * (2 * FFD) + FFD + c];
        float gl = 0.5f * gt * (1.f + erff(gt * 0.70710678118654752440f));
        g_gg[idx] = a * gl;
    }
}

// ----------------------- host orchestration ---------------------------------
struct TCPtrs {
    __nv_bfloat16 *ah, *al, *bh, *bl;
};

static void tc_gemm(const TCPtrs& p, const float* bias, const float* res,
                    float* C, int M, int N, int K) {
    static bool attr_set = false;
    if (!attr_set) {
        cudaFuncSetAttribute(tc_gemm_kernel, cudaFuncAttributeMaxDynamicSharedMemorySize,
                             TC_SMEM_TOTAL);
        attr_set = true;
    }
    dim3 grid(N / 128, (M + 127) / 128);
    tc_gemm_kernel<<<grid, 256, TC_SMEM_TOTAL>>>(p.ah, p.al, p.bh, p.bl,
                                                 bias, res, C, M, N, K);
}

static void convert_A(const float* x, size_t n, __nv_bfloat16* h, __nv_bfloat16* l) {
    convert_split_kernel<<<2048, 256>>>(x, n / 4, h, l);
}

static void trans_W(const float* W, int K, int N, __nv_bfloat16* Th, __nv_bfloat16* Tl) {
    wt_trans_split_kernel<<<dim3(N / 32, K / 32), 256>>>(W, K, N, Th, Tl);
}

extern "C" void kernel_launch(void* const* d_in, const int* in_sizes, int n_in,
                              void* d_out, int out_size) {
    (void)in_sizes; (void)n_in; (void)out_size;
    const float* hs    = (const float*)d_in[0];
    const float* enc   = (const float*)d_in[1];
    const float* ln1g  = (const float*)d_in[2];
    const float* ln1b  = (const float*)d_in[3];
    const float* Wq1   = (const float*)d_in[4];
    const float* Wk1   = (const float*)d_in[5];
    const float* Wv1   = (const float*)d_in[6];
    const float* Wo1   = (const float*)d_in[7];
    const float* bo1   = (const float*)d_in[8];
    const float* ln2g  = (const float*)d_in[9];
    const float* ln2b  = (const float*)d_in[10];
    const float* Wq2   = (const float*)d_in[11];
    const float* Wk2   = (const float*)d_in[12];
    const float* Wv2   = (const float*)d_in[13];
    const float* Wo2   = (const float*)d_in[14];
    const float* bo2   = (const float*)d_in[15];
    const float* ln3g  = (const float*)d_in[16];
    const float* ln3b  = (const float*)d_in[17];
    const float* Wff1  = (const float*)d_in[18];
    const float* bff1  = (const float*)d_in[19];
    const float* Wff2  = (const float*)d_in[20];
    const float* bff2  = (const float*)d_in[21];
    float* out = (float*)d_out;

    void* p;
    cudaGetSymbolAddress(&p, g_n);    float* n_   = (float*)p;
    cudaGetSymbolAddress(&p, g_q);    float* q_   = (float*)p;
    cudaGetSymbolAddress(&p, g_k);    float* k_   = (float*)p;
    cudaGetSymbolAddress(&p, g_v);    float* v_   = (float*)p;
    cudaGetSymbolAddress(&p, g_attn); float* at_  = (float*)p;
    cudaGetSymbolAddress(&p, g_proj); float* pj_  = (float*)p;
    cudaGetSymbolAddress(&p, g_gg);   float* gg_  = (float*)p;
    TCPtrs tc;
    cudaGetSymbolAddress(&p, g_ah);   tc.ah = (__nv_bfloat16*)p;
    cudaGetSymbolAddress(&p, g_al);   tc.al = (__nv_bfloat16*)p;
    cudaGetSymbolAddress(&p, g_bh);   tc.bh = (__nv_bfloat16*)p;
    cudaGetSymbolAddress(&p, g_bl);   tc.bl = (__nv_bfloat16*)p;

    const float scale = 1.0f / sqrtf((float)HDIM);
    const size_t nQ = (size_t)ROWS * DMODEL;
    const size_t nE = (size_t)ENCROWS * DMODEL;

    // ================= self-attention =================
    ln_kernel<<<ROWS, 256>>>(hs, ln1g, ln1b, n_);
    convert_A(n_, nQ, tc.ah, tc.al);
    trans_W(Wq1, DMODEL, DMODEL, tc.bh, tc.bl);
    tc_gemm(tc, nullptr, nullptr, q_, ROWS, DMODEL, DMODEL);
    trans_W(Wk1, DMODEL, DMODEL, tc.bh, tc.bl);
    tc_gemm(tc, nullptr, nullptr, k_, ROWS, DMODEL, DMODEL);
    trans_W(Wv1, DMODEL, DMODEL, tc.bh, tc.bl);
    tc_gemm(tc, nullptr, nullptr, v_, ROWS, DMODEL, DMODEL);
    init_stats_kernel<<<1, 32>>>();
    minmax_kernel<<<512, 256>>>(q_, nQ, 0);
    minmax_kernel<<<512, 256>>>(k_, nQ, 1);
    minmax_kernel<<<512, 256>>>(v_, nQ, 2);
    quant_kernel<<<2048, 256>>>(q_, nQ, 0);
    quant_kernel<<<2048, 256>>>(k_, nQ, 1);
    quant_kernel<<<2048, 256>>>(v_, nQ, 2);
    scores_kernel<<<dim3(SEQ / 64, SEQ / 64, BH), 256>>>(q_, k_, SEQ, scale);
    softmax_stats_kernel<<<NROWSBH, 128>>>(SEQ);
    maxinv_kernel<<<64, 256>>>();
    pv_kernel<<<dim3(SEQ / 128, BH), 256>>>(v_, SEQ);
    convert_A(at_, nQ, tc.ah, tc.al);
    trans_W(Wo1, DMODEL, DMODEL, tc.bh, tc.bl);
    tc_gemm(tc, bo1, hs, out, ROWS, DMODEL, DMODEL);

    // ================= cross-attention =================
    ln_kernel<<<ROWS, 256>>>(out, ln2g, ln2b, n_);
    convert_A(n_, nQ, tc.ah, tc.al);
    trans_W(Wq2, DMODEL, DMODEL, tc.bh, tc.bl);
    tc_gemm(tc, nullptr, nullptr, q_, ROWS, DMODEL, DMODEL);
    convert_A(enc, nE, tc.ah, tc.al);
    trans_W(Wk2, DMODEL, DMODEL, tc.bh, tc.bl);
    tc_gemm(tc, nullptr, nullptr, k_, ENCROWS, DMODEL, DMODEL);
    trans_W(Wv2, DMODEL, DMODEL, tc.bh, tc.bl);
    tc_gemm(tc, nullptr, nullptr, v_, ENCROWS, DMODEL, DMODEL);
    init_stats_kernel<<<1, 32>>>();
    minmax_kernel<<<512, 256>>>(q_, nQ, 0);
    minmax_kernel<<<512, 256>>>(k_, nE, 1);
    minmax_kernel<<<512, 256>>>(v_, nE, 2);
    quant_kernel<<<2048, 256>>>(q_, nQ, 0);
    quant_kernel<<<512, 256>>>(k_, nE, 1);
    quant_kernel<<<512, 256>>>(v_, nE, 2);
    scores_kernel<<<dim3((SENC + 63) / 64, SEQ / 64, BH), 256>>>(q_, k_, SENC, scale);
    softmax_stats_kernel<<<NROWSBH, 128>>>(SENC);
    maxinv_kernel<<<64, 256>>>();
    pv_kernel<<<dim3(SEQ / 128, BH), 256>>>(v_, SENC);
    convert_A(at_, nQ, tc.ah, tc.al);
    trans_W(Wo2, DMODEL, DMODEL, tc.bh, tc.bl);
    tc_gemm(tc, bo2, out, out, ROWS, DMODEL, DMODEL);

    // ================= feed-forward (GEGLU) =================
    ln_kernel<<<ROWS, 256>>>(out, ln3g, ln3b, n_);
    convert_A(n_, nQ, tc.ah, tc.al);
    trans_W(Wff1, DMODEL, 2 * FFD, tc.bh, tc.bl);
    tc_gemm(tc, bff1, nullptr, pj_, ROWS, 2 * FFD, DMODEL);
    geglu_kernel<<<8192, 256>>>();
    convert_A(gg_, (size_t)ROWS * FFD, tc.ah, tc.al);
    trans_W(Wff2, FFD, DMODEL, tc.bh, tc.bl);
    tc_gemm(tc, bff2, out, out, ROWS, DMODEL, FFD);
}

// round 5
// speedup vs baseline: 1.9493x; 1.0688x over previous
#include <cuda_runtime.h>
#include <cuda_bf16.h>
#include <math.h>
#include <stdint.h>

// Problem dims
#define BATCH   8
#define SEQ     1024
#define DMODEL  1152
#define NHEAD   16
#define HDIM    72
#define SENC    77
#define FFD     4608
#define ROWS    (BATCH*SEQ)        // 8192
#define ENCROWS (BATCH*SENC)       // 616
#define BH      (BATCH*NHEAD)      // 128
#define NROWSBH (BH*SEQ)           // 131072

__device__ __forceinline__ uint32_t smem_to_u32(const void* smem_ptr) {
    uint32_t addr;
    asm("{ .reg .u64 tmp; cvta.to.shared.u64 tmp, %1; cvt.u32.u64 %0, tmp; }"
        : "=r"(addr) : "l"(smem_ptr));
    return addr;
}

// fast exp on the FMA pipe (no MUFU). x <= 0 expected; rel err ~2e-7.
__device__ __forceinline__ float fexp(float x) {
    float t = x * 1.4426950408889634f;
    t = fmaxf(t, -126.0f);
    float fi = floorf(t);
    float f = t - fi;
    float p = 1.3333558146e-3f;
    p = fmaf(p, f, 9.6181291076e-3f);
    p = fmaf(p, f, 5.5504108664e-2f);
    p = fmaf(p, f, 2.4022650695910e-1f);
    p = fmaf(p, f, 6.9314718055994e-1f);
    p = fmaf(p, f, 1.0f);
    return p * __int_as_float(((int)fi + 127) << 23);
}

// ----------------------- scratch (device globals; no runtime alloc) ---------
__device__ float g_n[(size_t)ROWS*DMODEL];
__device__ float g_q[(size_t)ROWS*DMODEL];
__device__ float g_k[(size_t)ROWS*DMODEL];
__device__ float g_v[(size_t)ROWS*DMODEL];
__device__ float g_attn[(size_t)ROWS*DMODEL];
__device__ float g_scores[(size_t)BH*SEQ*SEQ];       // 512MB; scores then probs
__device__ float g_rowInvZ[NROWSBH];
__device__ float g_proj[(size_t)ROWS*2*FFD];
__device__ float g_gg[(size_t)ROWS*FFD];
__device__ float g_stats[8];
// bf16 hi/lo operand buffers
__device__ __nv_bfloat16 g_ah[(size_t)ROWS*FFD];
__device__ __nv_bfloat16 g_al[(size_t)ROWS*FFD];
__device__ __nv_bfloat16 g_bh[(size_t)(2*FFD)*DMODEL];
__device__ __nv_bfloat16 g_bl[(size_t)(2*FFD)*DMODEL];

// ----------------------- atomic float min/max -------------------------------
__device__ __forceinline__ void atomicMaxF(float* a, float v) {
    if (v >= 0.f) atomicMax((int*)a, __float_as_int(v));
    else          atomicMin((unsigned int*)a, __float_as_uint(v));
}
__device__ __forceinline__ void atomicMinF(float* a, float v) {
    if (v >= 0.f) atomicMin((int*)a, __float_as_int(v));
    else          atomicMax((unsigned int*)a, __float_as_uint(v));
}

// ----------------------- LayerNorm ------------------------------------------
__global__ __launch_bounds__(256) void ln_kernel(
    const float* __restrict__ x, const float* __restrict__ g,
    const float* __restrict__ b, float* __restrict__ o)
{
    const int N = DMODEL;
    size_t row = blockIdx.x;
    const float* xr = x + row * N;
    float* orow = o + row * N;
    int tid = threadIdx.x;

    float lv[5];
    int cnt = 0;
    float s = 0.f;
    for (int i = tid; i < N; i += 256) { float t = xr[i]; lv[cnt++] = t; s += t; }

    __shared__ float sh[8];
    for (int ofs = 16; ofs; ofs >>= 1) s += __shfl_xor_sync(0xffffffffu, s, ofs);
    if ((tid & 31) == 0) sh[tid >> 5] = s;
    __syncthreads();
    float tot = 0.f;
    #pragma unroll
    for (int i = 0; i < 8; i++) tot += sh[i];
    float mu = tot * (1.f / (float)N);

    float vs = 0.f;
    for (int c = 0; c < cnt; c++) { float d = lv[c] - mu; vs += d * d; }
    __syncthreads();
    for (int ofs = 16; ofs; ofs >>= 1) vs += __shfl_xor_sync(0xffffffffu, vs, ofs);
    if ((tid & 31) == 0) sh[tid >> 5] = vs;
    __syncthreads();
    float vtot = 0.f;
    #pragma unroll
    for (int i = 0; i < 8; i++) vtot += sh[i];
    float inv = rsqrtf(vtot * (1.f / (float)N) + 1e-5f);

    int i = tid;
    for (int c = 0; c < cnt; c++, i += 256)
        orow[i] = (lv[c] - mu) * inv * g[i] + b[i];
}

// ----------------------- fp32 -> bf16 hi/lo split ----------------------------
__global__ __launch_bounds__(256) void convert_split_kernel(
    const float* __restrict__ x, size_t n4,
    __nv_bfloat16* __restrict__ h, __nv_bfloat16* __restrict__ l)
{
    for (size_t i = (size_t)blockIdx.x * blockDim.x + threadIdx.x; i < n4;
         i += (size_t)gridDim.x * blockDim.x) {
        float4 v = ((const float4*)x)[i];
        __nv_bfloat16 h0 = __float2bfloat16(v.x);
        __nv_bfloat16 h1 = __float2bfloat16(v.y);
        __nv_bfloat16 h2 = __float2bfloat16(v.z);
        __nv_bfloat16 h3 = __float2bfloat16(v.w);
        __nv_bfloat162* hp = (__nv_bfloat162*)h;
        __nv_bfloat162* lp = (__nv_bfloat162*)l;
        hp[2*i]   = __nv_bfloat162(h0, h1);
        hp[2*i+1] = __nv_bfloat162(h2, h3);
        lp[2*i]   = __nv_bfloat162(__float2bfloat16(v.x - __bfloat162float(h0)),
                                   __float2bfloat16(v.y - __bfloat162float(h1)));
        lp[2*i+1] = __nv_bfloat162(__float2bfloat16(v.z - __bfloat162float(h2)),
                                   __float2bfloat16(v.w - __bfloat162float(h3)));
    }
}

// ----------------------- weight transpose + hi/lo split ----------------------
// W: [K][N] fp32 row-major -> Th/Tl: [N][K] bf16
__global__ __launch_bounds__(256) void wt_trans_split_kernel(
    const float* __restrict__ W, int K, int N,
    __nv_bfloat16* __restrict__ Th, __nv_bfloat16* __restrict__ Tl)
{
    __shared__ float tile[32][33];
    int n0 = blockIdx.x * 32, k0 = blockIdx.y * 32;
    int tx = threadIdx.x & 31, ty = threadIdx.x >> 5;
    #pragma unroll
    for (int r = ty; r < 32; r += 8) {
        int k = k0 + r, n = n0 + tx;
        tile[r][tx] = (k < K && n < N) ? W[(size_t)k * N + n] : 0.f;
    }
    __syncthreads();
    #pragma unroll
    for (int r = ty; r < 32; r += 8) {
        int n = n0 + r, k = k0 + tx;
        if (n < N && k < K) {
            float x = tile[tx][r];
            __nv_bfloat16 hh = __float2bfloat16(x);
            Th[(size_t)n * K + k] = hh;
            Tl[(size_t)n * K + k] = __float2bfloat16(x - __bfloat162float(hh));
        }
    }
}

// ----------------------- mma.sync bf16x3 GEMM (3-stage pipeline) ------------
#define TC_STAGE_BYTES 40960
#define TC_STAGES 3
#define TC_SMEM_TOTAL (TC_STAGES*TC_STAGE_BYTES)

__device__ __forceinline__ void cp16(uint32_t dst, const void* src, uint32_t sz) {
    asm volatile("cp.async.cg.shared.global [%0], [%1], 16, %2;"
                 :: "r"(dst), "l"(src), "r"(sz) : "memory");
}
template<int NN> __device__ __forceinline__ void cpasync_wait() {
    asm volatile("cp.async.wait_group %0;" :: "n"(NN) : "memory");
}
__device__ __forceinline__ void ldsm_x4(uint32_t* r, uint32_t addr) {
    asm volatile("ldmatrix.sync.aligned.m8n8.x4.shared.b16 {%0,%1,%2,%3}, [%4];"
        : "=r"(r[0]), "=r"(r[1]), "=r"(r[2]), "=r"(r[3]) : "r"(addr));
}
__device__ __forceinline__ void mma_bf16(float* c, const uint32_t* a, const uint32_t* b) {
    asm volatile("mma.sync.aligned.m16n8k16.row.col.f32.bf16.bf16.f32 "
        "{%0,%1,%2,%3}, {%4,%5,%6,%7}, {%8,%9}, {%0,%1,%2,%3};"
        : "+f"(c[0]), "+f"(c[1]), "+f"(c[2]), "+f"(c[3])
        : "r"(a[0]), "r"(a[1]), "r"(a[2]), "r"(a[3]), "r"(b[0]), "r"(b[1]));
}

__device__ __forceinline__ void tc_load_stage(
    uint32_t sbase,
    const __nv_bfloat16* __restrict__ Ah, const __nv_bfloat16* __restrict__ Al,
    const __nv_bfloat16* __restrict__ Bh, const __nv_bfloat16* __restrict__ Bl,
    int m0, int M, int n0, int K, int k0, int tid)
{
    #pragma unroll
    for (int i = 0; i < 2; i++) {
        int c = tid + i * 256;
        int row = c >> 2, kc = c & 3;
        uint32_t soff = (uint32_t)(row * 80 + kc * 16);
        size_t goffA = (size_t)(m0 + row) * K + k0 + kc * 8;
        uint32_t szA = ((m0 + row) < M) ? 16u : 0u;
        cp16(sbase + soff,         Ah + goffA, szA);
        cp16(sbase + 10240 + soff, Al + goffA, szA);
        size_t goffB = (size_t)(n0 + row) * K + k0 + kc * 8;
        cp16(sbase + 20480 + soff, Bh + goffB, 16u);
        cp16(sbase + 30720 + soff, Bl + goffB, 16u);
    }
    asm volatile("cp.async.commit_group;" ::: "memory");
}

__global__ __launch_bounds__(256) void tc_gemm_kernel(
    const __nv_bfloat16* __restrict__ Ah, const __nv_bfloat16* __restrict__ Al,
    const __nv_bfloat16* __restrict__ Bh, const __nv_bfloat16* __restrict__ Bl,
    const float* __restrict__ bias, const float* __restrict__ res,
    float* __restrict__ C, int M, int N, int K)
{
    extern __shared__ char smem[];
    uint32_t sb = smem_to_u32(smem);
    int tid = threadIdx.x;
    int wid = tid >> 5, lane = tid & 31;
    int n0 = blockIdx.x * 128, m0 = blockIdx.y * 128;
    int wm = wid & 3, wn = wid >> 2;

    float acc[2][8][4];
    #pragma unroll
    for (int mt = 0; mt < 2; mt++)
        #pragma unroll
        for (int nt = 0; nt < 8; nt++)
            #pragma unroll
            for (int e = 0; e < 4; e++) acc[mt][nt][e] = 0.f;

    const int KT = K >> 5;    // k-tiles of 32 (always >= 3 here)

    tc_load_stage(sb,                      Ah, Al, Bh, Bl, m0, M, n0, K, 0,  tid);
    tc_load_stage(sb + TC_STAGE_BYTES,     Ah, Al, Bh, Bl, m0, M, n0, K, 32, tid);
    tc_load_stage(sb + 2 * TC_STAGE_BYTES, Ah, Al, Bh, Bl, m0, M, n0, K, 64, tid);

    int buf = 0;
    for (int t = 0; t < KT; t++) {
        if (t + 2 < KT)      cpasync_wait<2>();
        else if (t + 1 < KT) cpasync_wait<1>();
        else                 cpasync_wait<0>();
        __syncthreads();

        uint32_t base = sb + buf * TC_STAGE_BYTES;
        #pragma unroll
        for (int kk = 0; kk < 2; kk++) {
            uint32_t ah[2][4], al[2][4];
            #pragma unroll
            for (int mt = 0; mt < 2; mt++) {
                uint32_t arow = (uint32_t)(wm * 32 + mt * 16 + (lane & 15));
                uint32_t abyte = arow * 80 + kk * 32 + ((lane >> 4) << 4);
                ldsm_x4(ah[mt], base + abyte);
                ldsm_x4(al[mt], base + 10240 + abyte);
            }
            #pragma unroll
            for (int bp = 0; bp < 4; bp++) {
                uint32_t brow = (uint32_t)(wn * 64 + bp * 16 + (lane & 7) + (((lane >> 4) & 1) << 3));
                uint32_t bbyte = brow * 80 + kk * 32 + (((lane >> 3) & 1) << 4);
                uint32_t bh4[4], bl4[4];
                ldsm_x4(bh4, base + 20480 + bbyte);
                ldsm_x4(bl4, base + 30720 + bbyte);
                #pragma unroll
                for (int sub = 0; sub < 2; sub++) {
                    int nt = bp * 2 + sub;
                    #pragma unroll
                    for (int mt = 0; mt < 2; mt++) {
                        mma_bf16(acc[mt][nt], ah[mt], bh4 + sub * 2);
                        mma_bf16(acc[mt][nt], ah[mt], bl4 + sub * 2);
                        mma_bf16(acc[mt][nt], al[mt], bh4 + sub * 2);
                    }
                }
            }
        }
        __syncthreads();
        if (t + 3 < KT)
            tc_load_stage(base, Ah, Al, Bh, Bl, m0, M, n0, K, (t + 3) << 5, tid);
        buf = (buf + 1 == TC_STAGES) ? 0 : buf + 1;
    }

    // epilogue
    #pragma unroll
    for (int mt = 0; mt < 2; mt++) {
        int r0 = m0 + wm * 32 + mt * 16 + (lane >> 2);
        #pragma unroll
        for (int nt = 0; nt < 8; nt++) {
            int cc = n0 + wn * 64 + nt * 8 + (lane & 3) * 2;
            #pragma unroll
            for (int h = 0; h < 2; h++) {
                int r = r0 + h * 8;
                if (r >= M) continue;
                float2 o = make_float2(acc[mt][nt][h * 2], acc[mt][nt][h * 2 + 1]);
                if (bias) {
                    float2 bb = *(const float2*)(bias + cc);
                    o.x += bb.x; o.y += bb.y;
                }
                if (res) {
                    float2 rv = *(const float2*)(res + (size_t)r * N + cc);
                    o.x += rv.x; o.y += rv.y;
                }
                *(float2*)(C + (size_t)r * N + cc) = o;
            }
        }
    }
}

// ----------------------- stats init / minmax / quant ------------------------
__global__ void init_stats_kernel() {
    int t = threadIdx.x;
    if (t < 3) { g_stats[2 * t] = INFINITY; g_stats[2 * t + 1] = -INFINITY; }
    if (t == 3) g_stats[6] = 0.f;
}

__global__ __launch_bounds__(256) void minmax_kernel(const float* __restrict__ x, size_t n, int slot) {
    float mn = INFINITY, mx = -INFINITY;
    for (size_t i = (size_t)blockIdx.x * blockDim.x + threadIdx.x; i < n;
         i += (size_t)gridDim.x * blockDim.x) {
        float v = x[i];
        mn = fminf(mn, v);
        mx = fmaxf(mx, v);
    }
    __shared__ float smn[8], smx[8];
    int tid = threadIdx.x;
    for (int o = 16; o; o >>= 1) {
        mn = fminf(mn, __shfl_xor_sync(0xffffffffu, mn, o));
        mx = fmaxf(mx, __shfl_xor_sync(0xffffffffu, mx, o));
    }
    if ((tid & 31) == 0) { smn[tid >> 5] = mn; smx[tid >> 5] = mx; }
    __syncthreads();
    if (tid == 0) {
        for (int i = 1; i < 8; i++) { mn = fminf(mn, smn[i]); mx = fmaxf(mx, smx[i]); }
        atomicMinF(&g_stats[2 * slot], mn);
        atomicMaxF(&g_stats[2 * slot + 1], mx);
    }
}

__global__ __launch_bounds__(256) void quant_kernel(float* x, size_t n, int slot) {
    float mn = g_stats[2 * slot], mx = g_stats[2 * slot + 1];
    float delta = (mx - mn) * (1.f / 255.f);
    float zp = rintf(-mn / delta);
    for (size_t i = (size_t)blockIdx.x * blockDim.x + threadIdx.x; i < n;
         i += (size_t)gridDim.x * blockDim.x) {
        float q = rintf(x[i] / delta) + zp;
        q = fminf(fmaxf(q, 0.f), 255.f);
        x[i] = (q - zp) * delta;
    }
}

// ----------------------- scores = scale * Q @ K^T (batched over B*H) --------
__global__ __launch_bounds__(256) void scores_kernel(
    const float* __restrict__ q, const float* __restrict__ kt, int SK, float scale)
{
    int bh = blockIdx.z, b = bh >> 4, h = bh & 15;
    const float* qb = q + ((size_t)b * SEQ) * DMODEL + h * HDIM;
    const float* kb = kt + ((size_t)b * SK) * DMODEL + h * HDIM;
    __shared__ float qs[72 * 68];
    __shared__ float ks[72 * 68];
    int tid = threadIdx.x;
    int qrow0 = blockIdx.y * 64, kcol0 = blockIdx.x * 64;

    for (int idx = tid; idx < 64 * 72; idx += 256) {
        int r = idx / 72, kk = idx % 72;
        qs[kk * 68 + r] = qb[(size_t)(qrow0 + r) * DMODEL + kk];
        int kr = kcol0 + r;
        ks[kk * 68 + r] = (kr < SK) ? kb[(size_t)kr * DMODEL + kk] : 0.f;
    }
    __syncthreads();

    int tx = tid & 15, ty = tid >> 4;
    float acc[4][4];
    #pragma unroll
    for (int i = 0; i < 4; i++)
        #pragma unroll
        for (int j = 0; j < 4; j++) acc[i][j] = 0.f;

    #pragma unroll 4
    for (int kk = 0; kk < 72; kk++) {
        float4 qv = *(const float4*)&qs[kk * 68 + ty * 4];
        float4 kv = *(const float4*)&ks[kk * 68 + tx * 4];
        float qa[4] = {qv.x, qv.y, qv.z, qv.w};
        float ka[4] = {kv.x, kv.y, kv.z, kv.w};
        #pragma unroll
        for (int i = 0; i < 4; i++)
            #pragma unroll
            for (int j = 0; j < 4; j++)
                acc[i][j] += qa[i] * ka[j];
    }

    #pragma unroll
    for (int i = 0; i < 4; i++) {
        int row = qrow0 + ty * 4 + i;
        size_t base = ((size_t)bh * SEQ + row) * SK;
        #pragma unroll
        for (int j = 0; j < 4; j++) {
            int col = kcol0 + tx * 4 + j;
            if (col < SK) g_scores[base + col] = acc[i][j] * scale;
        }
    }
}

// ----------------------- softmax: scores -> probs in-place ------------------
// Per-row: m, z via FMA-pipe exp; writes normalized probs back; saves invZ.
__global__ __launch_bounds__(128) void softmax_norm_kernel(int SK) {
    size_t row = blockIdx.x;
    float* sr = g_scores + row * (size_t)SK;
    int tid = threadIdx.x;
    float vals[8];
    int cnt = 0;
    float m = -INFINITY;
    for (int i = tid; i < SK; i += 128) { float t = sr[i]; vals[cnt++] = t; m = fmaxf(m, t); }

    __shared__ float sh[4];
    for (int o = 16; o; o >>= 1) m = fmaxf(m, __shfl_xor_sync(0xffffffffu, m, o));
    if ((tid & 31) == 0) sh[tid >> 5] = m;
    __syncthreads();
    m = fmaxf(fmaxf(sh[0], sh[1]), fmaxf(sh[2], sh[3]));

    float pv[8];
    float z = 0.f;
    for (int c = 0; c < cnt; c++) { pv[c] = fexp(vals[c] - m); z += pv[c]; }
    __syncthreads();
    for (int o = 16; o; o >>= 1) z += __shfl_xor_sync(0xffffffffu, z, o);
    __shared__ float sh2[4];
    if ((tid & 31) == 0) sh2[tid >> 5] = z;
    __syncthreads();
    float invZ = 1.f / (sh2[0] + sh2[1] + sh2[2] + sh2[3]);
    if (tid == 0) g_rowInvZ[row] = invZ;

    int i = tid;
    for (int c = 0; c < cnt; c++, i += 128) sr[i] = pv[c] * invZ;
}

__global__ __launch_bounds__(256) void maxinv_kernel() {
    float m = 0.f;
    for (int i = blockIdx.x * blockDim.x + threadIdx.x; i < NROWSBH;
         i += gridDim.x * blockDim.x)
        m = fmaxf(m, g_rowInvZ[i]);
    __shared__ float sh[8];
    int tid = threadIdx.x;
    for (int o = 16; o; o >>= 1) m = fmaxf(m, __shfl_xor_sync(0xffffffffu, m, o));
    if ((tid & 31) == 0) sh[tid >> 5] = m;
    __syncthreads();
    if (tid == 0) {
        for (int i = 1; i < 8; i++) m = fmaxf(m, sh[i]);
        atomicMaxF(&g_stats[6], m);
    }
}

// ----------------------- out = quantprobs @ V (probs precomputed) -----------
__global__ __launch_bounds__(256) void pv_kernel(const float* __restrict__ v, int SK) {
    int bh = blockIdx.y, b = bh >> 4, h = bh & 15;
    int m0 = blockIdx.x * 128;
    size_t rowbase = (size_t)bh * SEQ + m0;
    const float* vb = v + ((size_t)b * SK) * DMODEL + h * HDIM;

    float pmax = g_stats[6];
    float dp = pmax * (1.f / 255.f);
    float idp = 255.f / pmax;

    __shared__ float ps[32 * 132];
    __shared__ float vs[32 * 72];
    int tid = threadIdx.x;
    int tx = tid & 7, ty = tid >> 3;

    float acc[4][9];
    #pragma unroll
    for (int i = 0; i < 4; i++)
        #pragma unroll
        for (int j = 0; j < 9; j++) acc[i][j] = 0.f;

    for (int k0 = 0; k0 < SK; k0 += 32) {
        for (int idx = tid; idx < 128 * 32; idx += 256) {
            int r = idx >> 5, kk = idx & 31;
            int kg = k0 + kk;
            float pq = 0.f;
            if (kg < SK) {
                float p = g_scores[(rowbase + r) * SK + kg];
                pq = fminf(rintf(p * idp), 255.f) * dp;
            }
            ps[kk * 132 + r] = pq;
        }
        for (int idx = tid; idx < 32 * 72; idx += 256) {
            int kk = idx / 72, c = idx % 72;
            int kg = k0 + kk;
            vs[idx] = (kg < SK) ? vb[(size_t)kg * DMODEL + c] : 0.f;
        }
        __syncthreads();
        #pragma unroll 4
        for (int kk = 0; kk < 32; kk++) {
            float4 p4 = *(const float4*)&ps[kk * 132 + ty * 4];
            float pr[4] = {p4.x, p4.y, p4.z, p4.w};
            #pragma unroll
            for (int j = 0; j < 9; j++) {
                float vv = vs[kk * 72 + tx * 9 + j];
                #pragma unroll
                for (int i = 0; i < 4; i++) acc[i][j] += pr[i] * vv;
            }
        }
        __syncthreads();
    }

    #pragma unroll
    for (int i = 0; i < 4; i++) {
        int row = m0 + ty * 4 + i;
        size_t base = ((size_t)b * SEQ + row) * DMODEL + h * HDIM + tx * 9;
        #pragma unroll
        for (int j = 0; j < 9; j++) g_attn[base + j] = acc[i][j];
    }
}

// ----------------------- GEGLU ----------------------------------------------
__global__ __launch_bounds__(256) void geglu_kernel() {
    size_t n = (size_t)ROWS * FFD;
    for (size_t idx = (size_t)blockIdx.x * blockDim.x + threadIdx.x; idx < n;
         idx += (size_t)gridDim.x * blockDim.x) {
        size_t row = idx / FFD;
        int c = (int)(idx % FFD);
        float a  = g_proj[row * (2 * FFD) + c];
        float gt = g_proj[row * (2 * FFD) + FFD + c];
        float gl = 0.5f * gt * (1.f + erff(gt * 0.70710678118654752440f));
        g_gg[idx] = a * gl;
    }
}

// ----------------------- host orchestration ---------------------------------
struct TCPtrs {
    __nv_bfloat16 *ah, *al, *bh, *bl;
};

static void tc_gemm(const TCPtrs& p, const float* bias, const float* res,
                    float* C, int M, int N, int K) {
    static bool attr_set = false;
    if (!attr_set) {
        cudaFuncSetAttribute(tc_gemm_kernel, cudaFuncAttributeMaxDynamicSharedMemorySize,
                             TC_SMEM_TOTAL);
        attr_set = true;
    }
    dim3 grid(N / 128, (M + 127) / 128);
    tc_gemm_kernel<<<grid, 256, TC_SMEM_TOTAL>>>(p.ah, p.al, p.bh, p.bl,
                                                 bias, res, C, M, N, K);
}

static void convert_A(const float* x, size_t n, __nv_bfloat16* h, __nv_bfloat16* l) {
    convert_split_kernel<<<2048, 256>>>(x, n / 4, h, l);
}

static void trans_W(const float* W, int K, int N, __nv_bfloat16* Th, __nv_bfloat16* Tl) {
    wt_trans_split_kernel<<<dim3(N / 32, K / 32), 256>>>(W, K, N, Th, Tl);
}

extern "C" void kernel_launch(void* const* d_in, const int* in_sizes, int n_in,
                              void* d_out, int out_size) {
    (void)in_sizes; (void)n_in; (void)out_size;
    const float* hs    = (const float*)d_in[0];
    const float* enc   = (const float*)d_in[1];
    const float* ln1g  = (const float*)d_in[2];
    const float* ln1b  = (const float*)d_in[3];
    const float* Wq1   = (const float*)d_in[4];
    const float* Wk1   = (const float*)d_in[5];
    const float* Wv1   = (const float*)d_in[6];
    const float* Wo1   = (const float*)d_in[7];
    const float* bo1   = (const float*)d_in[8];
    const float* ln2g  = (const float*)d_in[9];
    const float* ln2b  = (const float*)d_in[10];
    const float* Wq2   = (const float*)d_in[11];
    const float* Wk2   = (const float*)d_in[12];
    const float* Wv2   = (const float*)d_in[13];
    const float* Wo2   = (const float*)d_in[14];
    const float* bo2   = (const float*)d_in[15];
    const float* ln3g  = (const float*)d_in[16];
    const float* ln3b  = (const float*)d_in[17];
    const float* Wff1  = (const float*)d_in[18];
    const float* bff1  = (const float*)d_in[19];
    const float* Wff2  = (const float*)d_in[20];
    const float* bff2  = (const float*)d_in[21];
    float* out = (float*)d_out;

    void* p;
    cudaGetSymbolAddress(&p, g_n);    float* n_   = (float*)p;
    cudaGetSymbolAddress(&p, g_q);    float* q_   = (float*)p;
    cudaGetSymbolAddress(&p, g_k);    float* k_   = (float*)p;
    cudaGetSymbolAddress(&p, g_v);    float* v_   = (float*)p;
    cudaGetSymbolAddress(&p, g_attn); float* at_  = (float*)p;
    cudaGetSymbolAddress(&p, g_proj); float* pj_  = (float*)p;
    cudaGetSymbolAddress(&p, g_gg);   float* gg_  = (float*)p;
    TCPtrs tc;
    cudaGetSymbolAddress(&p, g_ah);   tc.ah = (__nv_bfloat16*)p;
    cudaGetSymbolAddress(&p, g_al);   tc.al = (__nv_bfloat16*)p;
    cudaGetSymbolAddress(&p, g_bh);   tc.bh = (__nv_bfloat16*)p;
    cudaGetSymbolAddress(&p, g_bl);   tc.bl = (__nv_bfloat16*)p;

    const float scale = 1.0f / sqrtf((float)HDIM);
    const size_t nQ = (size_t)ROWS * DMODEL;
    const size_t nE = (size_t)ENCROWS * DMODEL;

    // ================= self-attention =================
    ln_kernel<<<ROWS, 256>>>(hs, ln1g, ln1b, n_);
    convert_A(n_, nQ, tc.ah, tc.al);
    trans_W(Wq1, DMODEL, DMODEL, tc.bh, tc.bl);
    tc_gemm(tc, nullptr, nullptr, q_, ROWS, DMODEL, DMODEL);
    trans_W(Wk1, DMODEL, DMODEL, tc.bh, tc.bl);
    tc_gemm(tc, nullptr, nullptr, k_, ROWS, DMODEL, DMODEL);
    trans_W(Wv1, DMODEL, DMODEL, tc.bh, tc.bl);
    tc_gemm(tc, nullptr, nullptr, v_, ROWS, DMODEL, DMODEL);
    init_stats_kernel<<<1, 32>>>();
    minmax_kernel<<<512, 256>>>(q_, nQ, 0);
    minmax_kernel<<<512, 256>>>(k_, nQ, 1);
    minmax_kernel<<<512, 256>>>(v_, nQ, 2);
    quant_kernel<<<2048, 256>>>(q_, nQ, 0);
    quant_kernel<<<2048, 256>>>(k_, nQ, 1);
    quant_kernel<<<2048, 256>>>(v_, nQ, 2);
    scores_kernel<<<dim3(SEQ / 64, SEQ / 64, BH), 256>>>(q_, k_, SEQ, scale);
    softmax_norm_kernel<<<NROWSBH, 128>>>(SEQ);
    maxinv_kernel<<<64, 256>>>();
    pv_kernel<<<dim3(SEQ / 128, BH), 256>>>(v_, SEQ);
    convert_A(at_, nQ, tc.ah, tc.al);
    trans_W(Wo1, DMODEL, DMODEL, tc.bh, tc.bl);
    tc_gemm(tc, bo1, hs, out, ROWS, DMODEL, DMODEL);

    // ================= cross-attention =================
    ln_kernel<<<ROWS, 256>>>(out, ln2g, ln2b, n_);
    convert_A(n_, nQ, tc.ah, tc.al);
    trans_W(Wq2, DMODEL, DMODEL, tc.bh, tc.bl);
    tc_gemm(tc, nullptr, nullptr, q_, ROWS, DMODEL, DMODEL);
    convert_A(enc, nE, tc.ah, tc.al);
    trans_W(Wk2, DMODEL, DMODEL, tc.bh, tc.bl);
    tc_gemm(tc, nullptr, nullptr, k_, ENCROWS, DMODEL, DMODEL);
    trans_W(Wv2, DMODEL, DMODEL, tc.bh, tc.bl);
    tc_gemm(tc, nullptr, nullptr, v_, ENCROWS, DMODEL, DMODEL);
    init_stats_kernel<<<1, 32>>>();
    minmax_kernel<<<512, 256>>>(q_, nQ, 0);
    minmax_kernel<<<512, 256>>>(k_, nE, 1);
    minmax_kernel<<<512, 256>>>(v_, nE, 2);
    quant_kernel<<<2048, 256>>>(q_, nQ, 0);
    quant_kernel<<<512, 256>>>(k_, nE, 1);
    quant_kernel<<<512, 256>>>(v_, nE, 2);
    scores_kernel<<<dim3((SENC + 63) / 64, SEQ / 64, BH), 256>>>(q_, k_, SENC, scale);
    softmax_norm_kernel<<<NROWSBH, 128>>>(SENC);
    maxinv_kernel<<<64, 256>>>();
    pv_kernel<<<dim3(SEQ / 128, BH), 256>>>(v_, SENC);
    convert_A(at_, nQ, tc.ah, tc.al);
    trans_W(Wo2, DMODEL, DMODEL, tc.bh, tc.bl);
    tc_gemm(tc, bo2, out, out, ROWS, DMODEL, DMODEL);

    // ================= feed-forward (GEGLU) =================
    ln_kernel<<<ROWS, 256>>>(out, ln3g, ln3b, n_);
    convert_A(n_, nQ, tc.ah, tc.al);
    trans_W(Wff1, DMODEL, 2 * FFD, tc.bh, tc.bl);
    tc_gemm(tc, bff1, nullptr, pj_, ROWS, 2 * FFD, DMODEL);
    geglu_kernel<<<8192, 256>>>();
    convert_A(gg_, (size_t)ROWS * FFD, tc.ah, tc.al);
    trans_W(Wff2, FFD, DMODEL, tc.bh, tc.bl);
    tc_gemm(tc, bff2, out, out, ROWS, DMODEL, FFD);
}

// round 6
// speedup vs baseline: 2.5171x; 1.2913x over previous
#include <cuda_runtime.h>
#include <cuda_bf16.h>
#include <math.h>
#include <stdint.h>

// Problem dims
#define BATCH   8
#define SEQ     1024
#define DMODEL  1152
#define NHEAD   16
#define HDIM    72
#define SENC    77
#define FFD     4608
#define ROWS    (BATCH*SEQ)        // 8192
#define ENCROWS (BATCH*SENC)       // 616
#define BH      (BATCH*NHEAD)      // 128
#define NROWSBH (BH*SEQ)           // 131072

__device__ __forceinline__ uint32_t smem_to_u32(const void* smem_ptr) {
    uint32_t addr;
    asm("{ .reg .u64 tmp; cvta.to.shared.u64 tmp, %1; cvt.u32.u64 %0, tmp; }"
        : "=r"(addr) : "l"(smem_ptr));
    return addr;
}

// fast exp on the FMA pipe (no MUFU). x <= 0 expected; rel err ~2e-7.
__device__ __forceinline__ float fexp(float x) {
    float t = x * 1.4426950408889634f;
    t = fmaxf(t, -126.0f);
    float fi = floorf(t);
    float f = t - fi;
    float p = 1.3333558146e-3f;
    p = fmaf(p, f, 9.6181291076e-3f);
    p = fmaf(p, f, 5.5504108664e-2f);
    p = fmaf(p, f, 2.4022650695910e-1f);
    p = fmaf(p, f, 6.9314718055994e-1f);
    p = fmaf(p, f, 1.0f);
    return p * __int_as_float(((int)fi + 127) << 23);
}

// ----------------------- scratch (device globals; no runtime alloc) ---------
__device__ float g_n[(size_t)ROWS*DMODEL];
__device__ float g_q[(size_t)ROWS*DMODEL];
__device__ float g_k[(size_t)ROWS*DMODEL];
__device__ float g_v[(size_t)ROWS*DMODEL];
__device__ float g_attn[(size_t)ROWS*DMODEL];
__device__ float g_scores[(size_t)BH*SEQ*SEQ];       // scores then probs (fp32)
__device__ float g_rowInvZ[NROWSBH];
__device__ float g_proj[(size_t)ROWS*2*FFD];
__device__ float g_gg[(size_t)ROWS*FFD];
__device__ float g_stats[8];
// bf16 hi/lo operand buffers (weight GEMMs)
__device__ __nv_bfloat16 g_ah[(size_t)ROWS*FFD];
__device__ __nv_bfloat16 g_al[(size_t)ROWS*FFD];
__device__ __nv_bfloat16 g_bh[(size_t)(2*FFD)*DMODEL];
__device__ __nv_bfloat16 g_bl[(size_t)(2*FFD)*DMODEL];
// integer-bf16 attention operands
__device__ __nv_bfloat16 g_qi[(size_t)BH*1024*80];
__device__ __nv_bfloat16 g_ki[(size_t)BH*1024*80];
__device__ __nv_bfloat16 g_vi[(size_t)BH*128*1024];
__device__ __nv_bfloat16 g_pi[(size_t)NROWSBH*1024];

// ----------------------- atomic float min/max -------------------------------
__device__ __forceinline__ void atomicMaxF(float* a, float v) {
    if (v >= 0.f) atomicMax((int*)a, __float_as_int(v));
    else          atomicMin((unsigned int*)a, __float_as_uint(v));
}
__device__ __forceinline__ void atomicMinF(float* a, float v) {
    if (v >= 0.f) atomicMin((int*)a, __float_as_int(v));
    else          atomicMax((unsigned int*)a, __float_as_uint(v));
}

// ----------------------- LayerNorm ------------------------------------------
__global__ __launch_bounds__(256) void ln_kernel(
    const float* __restrict__ x, const float* __restrict__ g,
    const float* __restrict__ b, float* __restrict__ o)
{
    const int N = DMODEL;
    size_t row = blockIdx.x;
    const float* xr = x + row * N;
    float* orow = o + row * N;
    int tid = threadIdx.x;

    float lv[5];
    int cnt = 0;
    float s = 0.f;
    for (int i = tid; i < N; i += 256) { float t = xr[i]; lv[cnt++] = t; s += t; }

    __shared__ float sh[8];
    for (int ofs = 16; ofs; ofs >>= 1) s += __shfl_xor_sync(0xffffffffu, s, ofs);
    if ((tid & 31) == 0) sh[tid >> 5] = s;
    __syncthreads();
    float tot = 0.f;
    #pragma unroll
    for (int i = 0; i < 8; i++) tot += sh[i];
    float mu = tot * (1.f / (float)N);

    float vs = 0.f;
    for (int c = 0; c < cnt; c++) { float d = lv[c] - mu; vs += d * d; }
    __syncthreads();
    for (int ofs = 16; ofs; ofs >>= 1) vs += __shfl_xor_sync(0xffffffffu, vs, ofs);
    if ((tid & 31) == 0) sh[tid >> 5] = vs;
    __syncthreads();
    float vtot = 0.f;
    #pragma unroll
    for (int i = 0; i < 8; i++) vtot += sh[i];
    float inv = rsqrtf(vtot * (1.f / (float)N) + 1e-5f);

    int i = tid;
    for (int c = 0; c < cnt; c++, i += 256)
        orow[i] = (lv[c] - mu) * inv * g[i] + b[i];
}

// ----------------------- fp32 -> bf16 hi/lo split ----------------------------
__global__ __launch_bounds__(256) void convert_split_kernel(
    const float* __restrict__ x, size_t n4,
    __nv_bfloat16* __restrict__ h, __nv_bfloat16* __restrict__ l)
{
    for (size_t i = (size_t)blockIdx.x * blockDim.x + threadIdx.x; i < n4;
         i += (size_t)gridDim.x * blockDim.x) {
        float4 v = ((const float4*)x)[i];
        __nv_bfloat16 h0 = __float2bfloat16(v.x);
        __nv_bfloat16 h1 = __float2bfloat16(v.y);
        __nv_bfloat16 h2 = __float2bfloat16(v.z);
        __nv_bfloat16 h3 = __float2bfloat16(v.w);
        __nv_bfloat162* hp = (__nv_bfloat162*)h;
        __nv_bfloat162* lp = (__nv_bfloat162*)l;
        hp[2*i]   = __nv_bfloat162(h0, h1);
        hp[2*i+1] = __nv_bfloat162(h2, h3);
        lp[2*i]   = __nv_bfloat162(__float2bfloat16(v.x - __bfloat162float(h0)),
                                   __float2bfloat16(v.y - __bfloat162float(h1)));
        lp[2*i+1] = __nv_bfloat162(__float2bfloat16(v.z - __bfloat162float(h2)),
                                   __float2bfloat16(v.w - __bfloat162float(h3)));
    }
}

// ----------------------- weight transpose + hi/lo split ----------------------
__global__ __launch_bounds__(256) void wt_trans_split_kernel(
    const float* __restrict__ W, int K, int N,
    __nv_bfloat16* __restrict__ Th, __nv_bfloat16* __restrict__ Tl)
{
    __shared__ float tile[32][33];
    int n0 = blockIdx.x * 32, k0 = blockIdx.y * 32;
    int tx = threadIdx.x & 31, ty = threadIdx.x >> 5;
    #pragma unroll
    for (int r = ty; r < 32; r += 8) {
        int k = k0 + r, n = n0 + tx;
        tile[r][tx] = (k < K && n < N) ? W[(size_t)k * N + n] : 0.f;
    }
    __syncthreads();
    #pragma unroll
    for (int r = ty; r < 32; r += 8) {
        int n = n0 + r, k = k0 + tx;
        if (n < N && k < K) {
            float x = tile[tx][r];
            __nv_bfloat16 hh = __float2bfloat16(x);
            Th[(size_t)n * K + k] = hh;
            Tl[(size_t)n * K + k] = __float2bfloat16(x - __bfloat162float(hh));
        }
    }
}

// ----------------------- mma primitives -------------------------------------
__device__ __forceinline__ void cp16(uint32_t dst, const void* src, uint32_t sz) {
    asm volatile("cp.async.cg.shared.global [%0], [%1], 16, %2;"
                 :: "r"(dst), "l"(src), "r"(sz) : "memory");
}
template<int NN> __device__ __forceinline__ void cpasync_wait() {
    asm volatile("cp.async.wait_group %0;" :: "n"(NN) : "memory");
}
__device__ __forceinline__ void ldsm_x4(uint32_t* r, uint32_t addr) {
    asm volatile("ldmatrix.sync.aligned.m8n8.x4.shared.b16 {%0,%1,%2,%3}, [%4];"
        : "=r"(r[0]), "=r"(r[1]), "=r"(r[2]), "=r"(r[3]) : "r"(addr));
}
__device__ __forceinline__ void mma_bf16(float* c, const uint32_t* a, const uint32_t* b) {
    asm volatile("mma.sync.aligned.m16n8k16.row.col.f32.bf16.bf16.f32 "
        "{%0,%1,%2,%3}, {%4,%5,%6,%7}, {%8,%9}, {%0,%1,%2,%3};"
        : "+f"(c[0]), "+f"(c[1]), "+f"(c[2]), "+f"(c[3])
        : "r"(a[0]), "r"(a[1]), "r"(a[2]), "r"(a[3]), "r"(b[0]), "r"(b[1]));
}

// ----------------------- mma.sync bf16x3 GEMM (2-stage, 2 CTAs/SM) ----------
#define TC_STAGE_BYTES 40960
#define TC_SMEM_TOTAL  (2*TC_STAGE_BYTES)

__device__ __forceinline__ void tc_load_stage(
    uint32_t sbase,
    const __nv_bfloat16* __restrict__ Ah, const __nv_bfloat16* __restrict__ Al,
    const __nv_bfloat16* __restrict__ Bh, const __nv_bfloat16* __restrict__ Bl,
    int m0, int M, int n0, int K, int k0, int tid)
{
    #pragma unroll
    for (int i = 0; i < 2; i++) {
        int c = tid + i * 256;
        int row = c >> 2, kc = c & 3;
        uint32_t soff = (uint32_t)(row * 80 + kc * 16);
        size_t goffA = (size_t)(m0 + row) * K + k0 + kc * 8;
        uint32_t szA = ((m0 + row) < M) ? 16u : 0u;
        cp16(sbase + soff,         Ah + goffA, szA);
        cp16(sbase + 10240 + soff, Al + goffA, szA);
        size_t goffB = (size_t)(n0 + row) * K + k0 + kc * 8;
        cp16(sbase + 20480 + soff, Bh + goffB, 16u);
        cp16(sbase + 30720 + soff, Bl + goffB, 16u);
    }
    asm volatile("cp.async.commit_group;" ::: "memory");
}

__global__ __launch_bounds__(256, 2) void tc_gemm_kernel(
    const __nv_bfloat16* __restrict__ Ah, const __nv_bfloat16* __restrict__ Al,
    const __nv_bfloat16* __restrict__ Bh, const __nv_bfloat16* __restrict__ Bl,
    const float* __restrict__ bias, const float* __restrict__ res,
    float* __restrict__ C, int M, int N, int K)
{
    extern __shared__ char smem[];
    uint32_t sb = smem_to_u32(smem);
    int tid = threadIdx.x;
    int wid = tid >> 5, lane = tid & 31;
    int n0 = blockIdx.x * 128, m0 = blockIdx.y * 128;
    int wm = wid & 3, wn = wid >> 2;

    float acc[2][8][4];
    #pragma unroll
    for (int mt = 0; mt < 2; mt++)
        #pragma unroll
        for (int nt = 0; nt < 8; nt++)
            #pragma unroll
            for (int e = 0; e < 4; e++) acc[mt][nt][e] = 0.f;

    const int KT = K >> 5;

    tc_load_stage(sb, Ah, Al, Bh, Bl, m0, M, n0, K, 0, tid);

    for (int t = 0; t < KT; t++) {
        if (t + 1 < KT) {
            tc_load_stage(sb + ((t + 1) & 1) * TC_STAGE_BYTES,
                          Ah, Al, Bh, Bl, m0, M, n0, K, (t + 1) << 5, tid);
            cpasync_wait<1>();
        } else {
            cpasync_wait<0>();
        }
        __syncthreads();

        uint32_t base = sb + (t & 1) * TC_STAGE_BYTES;
        #pragma unroll
        for (int kk = 0; kk < 2; kk++) {
            uint32_t ah[2][4], al[2][4];
            #pragma unroll
            for (int mt = 0; mt < 2; mt++) {
                uint32_t arow = (uint32_t)(wm * 32 + mt * 16 + (lane & 15));
                uint32_t abyte = arow * 80 + kk * 32 + ((lane >> 4) << 4);
                ldsm_x4(ah[mt], base + abyte);
                ldsm_x4(al[mt], base + 10240 + abyte);
            }
            #pragma unroll
            for (int bp = 0; bp < 4; bp++) {
                uint32_t brow = (uint32_t)(wn * 64 + bp * 16 + (lane & 7) + (((lane >> 4) & 1) << 3));
                uint32_t bbyte = brow * 80 + kk * 32 + (((lane >> 3) & 1) << 4);
                uint32_t bh4[4], bl4[4];
                ldsm_x4(bh4, base + 20480 + bbyte);
                ldsm_x4(bl4, base + 30720 + bbyte);
                #pragma unroll
                for (int sub = 0; sub < 2; sub++) {
                    int nt = bp * 2 + sub;
                    #pragma unroll
                    for (int mt = 0; mt < 2; mt++) {
                        mma_bf16(acc[mt][nt], ah[mt], bh4 + sub * 2);
                        mma_bf16(acc[mt][nt], ah[mt], bl4 + sub * 2);
                        mma_bf16(acc[mt][nt], al[mt], bh4 + sub * 2);
                    }
                }
            }
        }
        __syncthreads();
    }

    #pragma unroll
    for (int mt = 0; mt < 2; mt++) {
        int r0 = m0 + wm * 32 + mt * 16 + (lane >> 2);
        #pragma unroll
        for (int nt = 0; nt < 8; nt++) {
            int cc = n0 + wn * 64 + nt * 8 + (lane & 3) * 2;
            #pragma unroll
            for (int h = 0; h < 2; h++) {
                int r = r0 + h * 8;
                if (r >= M) continue;
                float2 o = make_float2(acc[mt][nt][h * 2], acc[mt][nt][h * 2 + 1]);
                if (bias) {
                    float2 bb = *(const float2*)(bias + cc);
                    o.x += bb.x; o.y += bb.y;
                }
                if (res) {
                    float2 rv = *(const float2*)(res + (size_t)r * N + cc);
                    o.x += rv.x; o.y += rv.y;
                }
                *(float2*)(C + (size_t)r * N + cc) = o;
            }
        }
    }
}

// ----------------------- stats init / minmax --------------------------------
__global__ void init_stats_kernel() {
    int t = threadIdx.x;
    if (t < 3) { g_stats[2 * t] = INFINITY; g_stats[2 * t + 1] = -INFINITY; }
    if (t == 3) g_stats[6] = 0.f;
}

__global__ __launch_bounds__(256) void minmax_kernel(const float* __restrict__ x, size_t n, int slot) {
    float mn = INFINITY, mx = -INFINITY;
    for (size_t i = (size_t)blockIdx.x * blockDim.x + threadIdx.x; i < n;
         i += (size_t)gridDim.x * blockDim.x) {
        float v = x[i];
        mn = fminf(mn, v);
        mx = fmaxf(mx, v);
    }
    __shared__ float smn[8], smx[8];
    int tid = threadIdx.x;
    for (int o = 16; o; o >>= 1) {
        mn = fminf(mn, __shfl_xor_sync(0xffffffffu, mn, o));
        mx = fmaxf(mx, __shfl_xor_sync(0xffffffffu, mx, o));
    }
    if ((tid & 31) == 0) { smn[tid >> 5] = mn; smx[tid >> 5] = mx; }
    __syncthreads();
    if (tid == 0) {
        for (int i = 1; i < 8; i++) { mn = fminf(mn, smn[i]); mx = fmaxf(mx, smx[i]); }
        atomicMinF(&g_stats[2 * slot], mn);
        atomicMaxF(&g_stats[2 * slot + 1], mx);
    }
}

// ----------------------- quantize to integer-bf16 ----------------------------
// Q/K: out[(bh*SPAD + s)*80 + d] = (clip(rint(x/delta)+zp,0,255) - zp), d>=72 or s>=S -> 0
__global__ __launch_bounds__(256) void quant_qk_kernel(
    const float* __restrict__ x, __nv_bfloat16* __restrict__ out,
    int S, int SPAD, int slot)
{
    int bh = blockIdx.y, s0 = blockIdx.x * 32;
    int b = bh >> 4, h = bh & 15;
    float mn = g_stats[2 * slot], mx = g_stats[2 * slot + 1];
    float delta = (mx - mn) * (1.f / 255.f);
    float zp = rintf(-mn / delta);
    #pragma unroll
    for (int it = 0; it < 10; it++) {
        int local = threadIdx.x + it * 256;
        int sl = local / 80, d = local % 80;
        int s = s0 + sl;
        float val = 0.f;
        if (d < 72 && s < S) {
            float xv = x[((size_t)b * S + s) * DMODEL + h * HDIM + d];
            float q = fminf(fmaxf(rintf(xv / delta) + zp, 0.f), 255.f);
            val = q - zp;
        }
        out[((size_t)bh * SPAD + s) * 80 + d] = __float2bfloat16(val);
    }
}

// V: out[(bh*128 + d)*SPAD + s] (transposed per head), d>=72 or s>=S -> 0
__global__ __launch_bounds__(256) void quant_v_kernel(
    const float* __restrict__ x, __nv_bfloat16* __restrict__ out,
    int S, int SPAD, int slot)
{
    int bh = blockIdx.y;
    int b = bh >> 4, h = bh & 15;
    int schunk = SPAD >> 3;
    int sbase = blockIdx.x * schunk;
    float mn = g_stats[2 * slot], mx = g_stats[2 * slot + 1];
    float delta = (mx - mn) * (1.f / 255.f);
    float zp = rintf(-mn / delta);
    for (int d = 0; d < 128; d++) {
        const float* src = x + ((size_t)b * S) * DMODEL + h * HDIM + d;
        __nv_bfloat16* dst = out + ((size_t)bh * 128 + d) * SPAD;
        for (int s = sbase + threadIdx.x; s < sbase + schunk; s += 256) {
            float val = 0.f;
            if (d < 72 && s < S) {
                float xv = src[(size_t)s * DMODEL];
                float q = fminf(fmaxf(rintf(xv / delta) + zp, 0.f), 255.f);
                val = q - zp;
            }
            dst[s] = __float2bfloat16(val);
        }
    }
}

// ----------------------- scores = premul*dq*dk * Iq @ Ik^T (bf16 MMA) -------
__global__ __launch_bounds__(256) void scores_mma_kernel(
    float* __restrict__ scores, int SK, int KROWS, float premul)
{
    __shared__ char sA[128 * 176];
    __shared__ char sB[128 * 176];
    int tid = threadIdx.x, wid = tid >> 5, lane = tid & 31;
    int bh = blockIdx.z;
    int kcol0 = blockIdx.x * 128, qrow0 = blockIdx.y * 128;
    int wm = wid & 3, wn = wid >> 2;
    uint32_t sa = smem_to_u32(sA), sb = smem_to_u32(sB);

    const __nv_bfloat16* qb = g_qi + ((size_t)bh * 1024 + qrow0) * 80;
    const __nv_bfloat16* kb = g_ki + ((size_t)bh * KROWS + kcol0) * 80;
    #pragma unroll
    for (int i = 0; i < 5; i++) {
        int c = tid + i * 256;
        int row = c / 10, j = c - row * 10;
        cp16(sa + row * 176 + j * 16, qb + (size_t)row * 80 + j * 8, 16u);
        cp16(sb + row * 176 + j * 16, kb + (size_t)row * 80 + j * 8, 16u);
    }
    asm volatile("cp.async.commit_group;" ::: "memory");
    cpasync_wait<0>();
    __syncthreads();

    float acc[2][8][4];
    #pragma unroll
    for (int mt = 0; mt < 2; mt++)
        #pragma unroll
        for (int nt = 0; nt < 8; nt++)
            #pragma unroll
            for (int e = 0; e < 4; e++) acc[mt][nt][e] = 0.f;

    #pragma unroll
    for (int kk = 0; kk < 5; kk++) {
        uint32_t af[2][4];
        #pragma unroll
        for (int mt = 0; mt < 2; mt++) {
            uint32_t arow = (uint32_t)(wm * 32 + mt * 16 + (lane & 15));
            ldsm_x4(af[mt], sa + arow * 176 + kk * 32 + ((lane >> 4) << 4));
        }
        #pragma unroll
        for (int bp = 0; bp < 4; bp++) {
            uint32_t brow = (uint32_t)(wn * 64 + bp * 16 + (lane & 7) + (((lane >> 4) & 1) << 3));
            uint32_t bf4[4];
            ldsm_x4(bf4, sb + brow * 176 + kk * 32 + (((lane >> 3) & 1) << 4));
            #pragma unroll
            for (int sub = 0; sub < 2; sub++) {
                int nt = bp * 2 + sub;
                #pragma unroll
                for (int mt = 0; mt < 2; mt++)
                    mma_bf16(acc[mt][nt], af[mt], bf4 + sub * 2);
            }
        }
    }

    float dq = (g_stats[1] - g_stats[0]) * (1.f / 255.f);
    float dk = (g_stats[3] - g_stats[2]) * (1.f / 255.f);
    float sc = dq * dk * premul;

    #pragma unroll
    for (int mt = 0; mt < 2; mt++) {
        int r0 = qrow0 + wm * 32 + mt * 16 + (lane >> 2);
        #pragma unroll
        for (int nt = 0; nt < 8; nt++) {
            int c0 = kcol0 + wn * 64 + nt * 8 + (lane & 3) * 2;
            #pragma unroll
            for (int h = 0; h < 2; h++) {
                int r = r0 + h * 8;
                size_t base = ((size_t)bh * SEQ + r) * SK;
                if (c0 < SK)     scores[base + c0]     = acc[mt][nt][h * 2]     * sc;
                if (c0 + 1 < SK) scores[base + c0 + 1] = acc[mt][nt][h * 2 + 1] * sc;
            }
        }
    }
}

// ----------------------- softmax: scores -> probs in-place ------------------
__global__ __launch_bounds__(128) void softmax_norm_kernel(int SK) {
    size_t row = blockIdx.x;
    float* sr = g_scores + row * (size_t)SK;
    int tid = threadIdx.x;
    float vals[8];
    int cnt = 0;
    float m = -INFINITY;
    for (int i = tid; i < SK; i += 128) { float t = sr[i]; vals[cnt++] = t; m = fmaxf(m, t); }

    __shared__ float sh[4];
    for (int o = 16; o; o >>= 1) m = fmaxf(m, __shfl_xor_sync(0xffffffffu, m, o));
    if ((tid & 31) == 0) sh[tid >> 5] = m;
    __syncthreads();
    m = fmaxf(fmaxf(sh[0], sh[1]), fmaxf(sh[2], sh[3]));

    float pv[8];
    float z = 0.f;
    for (int c = 0; c < cnt; c++) { pv[c] = fexp(vals[c] - m); z += pv[c]; }
    __syncthreads();
    for (int o = 16; o; o >>= 1) z += __shfl_xor_sync(0xffffffffu, z, o);
    __shared__ float sh2[4];
    if ((tid & 31) == 0) sh2[tid >> 5] = z;
    __syncthreads();
    float invZ = 1.f / (sh2[0] + sh2[1] + sh2[2] + sh2[3]);
    if (tid == 0) g_rowInvZ[row] = invZ;

    int i = tid;
    for (int c = 0; c < cnt; c++, i += 128) sr[i] = pv[c] * invZ;
}

__global__ __launch_bounds__(256) void maxinv_kernel() {
    float m = 0.f;
    for (int i = blockIdx.x * blockDim.x + threadIdx.x; i < NROWSBH;
         i += gridDim.x * blockDim.x)
        m = fmaxf(m, g_rowInvZ[i]);
    __shared__ float sh[8];
    int tid = threadIdx.x;
    for (int o = 16; o; o >>= 1) m = fmaxf(m, __shfl_xor_sync(0xffffffffu, m, o));
    if ((tid & 31) == 0) sh[tid >> 5] = m;
    __syncthreads();
    if (tid == 0) {
        for (int i = 1; i < 8; i++) m = fmaxf(m, sh[i]);
        atomicMaxF(&g_stats[6], m);
    }
}

// ----------------------- quantize probs to integer-bf16 ----------------------
__global__ __launch_bounds__(256) void quantp_kernel(int SK, int SKPAD) {
    size_t row = blockIdx.x;
    float idp = 255.f / g_stats[6];
    const float* src = g_scores + row * (size_t)SK;
    __nv_bfloat16* dst = g_pi + row * (size_t)SKPAD;
    for (int kc = threadIdx.x; kc < SKPAD; kc += 256) {
        float val = 0.f;
        if (kc < SK) val = fminf(rintf(src[kc] * idp), 255.f);
        dst[kc] = __float2bfloat16(val);
    }
}

// ----------------------- out = dp*dv * Ip @ Iv^T (bf16 MMA) -----------------
__global__ __launch_bounds__(256) void pv_mma_kernel(int SKPAD) {
    __shared__ char smem2[2][20480];
    int tid = threadIdx.x, wid = tid >> 5, lane = tid & 31;
    int bh = blockIdx.y, m0 = blockIdx.x * 128;
    int b = bh >> 4, h = bh & 15;
    int wm = wid & 3, wn = wid >> 2;
    uint32_t s0 = smem_to_u32(smem2);

    const __nv_bfloat16* pb = g_pi + ((size_t)bh * SEQ + m0) * SKPAD;
    const __nv_bfloat16* vb = g_vi + (size_t)bh * 128 * SKPAD;
    const int KT = SKPAD >> 5;

    float acc[2][8][4];
    #pragma unroll
    for (int mt = 0; mt < 2; mt++)
        #pragma unroll
        for (int nt = 0; nt < 8; nt++)
            #pragma unroll
            for (int e = 0; e < 4; e++) acc[mt][nt][e] = 0.f;

    // prologue load stage 0
    {
        #pragma unroll
        for (int i = 0; i < 2; i++) {
            int c = tid + i * 256;
            int row = c >> 2, j = c & 3;
            cp16(s0 + row * 80 + j * 16,         pb + (size_t)row * SKPAD + j * 8, 16u);
            cp16(s0 + 10240 + row * 80 + j * 16, vb + (size_t)row * SKPAD + j * 8, 16u);
        }
        asm volatile("cp.async.commit_group;" ::: "memory");
    }

    const int BPMAX = 4;   // wn==1 only needs bp 0 (cols >=72 are zero anyway)
    for (int t = 0; t < KT; t++) {
        if (t + 1 < KT) {
            uint32_t sn = s0 + ((t + 1) & 1) * 20480;
            int k0 = (t + 1) << 5;
            #pragma unroll
            for (int i = 0; i < 2; i++) {
                int c = tid + i * 256;
                int row = c >> 2, j = c & 3;
                cp16(sn + row * 80 + j * 16,         pb + (size_t)row * SKPAD + k0 + j * 8, 16u);
                cp16(sn + 10240 + row * 80 + j * 16, vb + (size_t)row * SKPAD + k0 + j * 8, 16u);
            }
            asm volatile("cp.async.commit_group;" ::: "memory");
            cpasync_wait<1>();
        } else {
            cpasync_wait<0>();
        }
        __syncthreads();

        uint32_t base = s0 + (t & 1) * 20480;
        #pragma unroll
        for (int kk = 0; kk < 2; kk++) {
            uint32_t af[2][4];
            #pragma unroll
            for (int mt = 0; mt < 2; mt++) {
                uint32_t arow = (uint32_t)(wm * 32 + mt * 16 + (lane & 15));
                ldsm_x4(af[mt], base + arow * 80 + kk * 32 + ((lane >> 4) << 4));
            }
            int bplim = (wn == 0) ? BPMAX : 1;
            for (int bp = 0; bp < bplim; bp++) {
                uint32_t brow = (uint32_t)(wn * 64 + bp * 16 + (lane & 7) + (((lane >> 4) & 1) << 3));
                uint32_t bf4[4];
                ldsm_x4(bf4, base + 10240 + brow * 80 + kk * 32 + (((lane >> 3) & 1) << 4));
                #pragma unroll
                for (int sub = 0; sub < 2; sub++) {
                    int nt = bp * 2 + sub;
                    #pragma unroll
                    for (int mt = 0; mt < 2; mt++)
                        mma_bf16(acc[mt][nt], af[mt], bf4 + sub * 2);
                }
            }
        }
        __syncthreads();
    }

    float dp = g_stats[6] * (1.f / 255.f);
    float dv = (g_stats[5] - g_stats[4]) * (1.f / 255.f);
    float sc = dp * dv;

    #pragma unroll
    for (int mt = 0; mt < 2; mt++) {
        int r0 = m0 + wm * 32 + mt * 16 + (lane >> 2);
        #pragma unroll
        for (int nt = 0; nt < 8; nt++) {
            int n = wn * 64 + nt * 8 + (lane & 3) * 2;
            if (n >= 72) continue;
            #pragma unroll
            for (int h2 = 0; h2 < 2; h2++) {
                int r = r0 + h2 * 8;
                float2 o = make_float2(acc[mt][nt][h2 * 2] * sc, acc[mt][nt][h2 * 2 + 1] * sc);
                *(float2*)(g_attn + ((size_t)b * SEQ + r) * DMODEL + h * HDIM + n) = o;
            }
        }
    }
}

// ----------------------- GEGLU ----------------------------------------------
__global__ __launch_bounds__(256) void geglu_kernel() {
    size_t n = (size_t)ROWS * FFD;
    for (size_t idx = (size_t)blockIdx.x * blockDim.x + threadIdx.x; idx < n;
         idx += (size_t)gridDim.x * blockDim.x) {
        size_t row = idx / FFD;
        int c = (int)(idx % FFD);
        float a  = g_proj[row * (2 * FFD) + c];
        float gt = g_proj[row * (2 * FFD) + FFD + c];
        float gl = 0.5f * gt * (1.f + erff(gt * 0.70710678118654752440f));
        g_gg[idx] = a * gl;
    }
}

// ----------------------- host orchestration ---------------------------------
struct TCPtrs {
    __nv_bfloat16 *ah, *al, *bh, *bl;
};

static void tc_gemm(const TCPtrs& p, const float* bias, const float* res,
                    float* C, int M, int N, int K) {
    static bool attr_set = false;
    if (!attr_set) {
        cudaFuncSetAttribute(tc_gemm_kernel, cudaFuncAttributeMaxDynamicSharedMemorySize,
                             TC_SMEM_TOTAL);
        attr_set = true;
    }
    dim3 grid(N / 128, (M + 127) / 128);
    tc_gemm_kernel<<<grid, 256, TC_SMEM_TOTAL>>>(p.ah, p.al, p.bh, p.bl,
                                                 bias, res, C, M, N, K);
}

static void convert_A(const float* x, size_t n, __nv_bfloat16* h, __nv_bfloat16* l) {
    convert_split_kernel<<<2048, 256>>>(x, n / 4, h, l);
}

static void trans_W(const float* W, int K, int N, __nv_bfloat16* Th, __nv_bfloat16* Tl) {
    wt_trans_split_kernel<<<dim3(N / 32, K / 32), 256>>>(W, K, N, Th, Tl);
}

// full quant+attention block: q_ is [B][SEQ] rows; k_/v_ are [B][S] rows
static void attention_block(const float* q_, const float* k_, const float* v_,
                            int S, int SPADK, float* scores_) {
    const size_t nQ = (size_t)ROWS * DMODEL;
    const size_t nKV = (size_t)(BATCH * S) * DMODEL;
    init_stats_kernel<<<1, 32>>>();
    minmax_kernel<<<512, 256>>>(q_, nQ, 0);
    minmax_kernel<<<512, 256>>>(k_, nKV, 1);
    minmax_kernel<<<512, 256>>>(v_, nKV, 2);
    quant_qk_kernel<<<dim3(1024 / 32, BH), 256>>>(q_, (__nv_bfloat16*)nullptr ? nullptr : nullptr, 0, 0, 0); // placeholder (replaced below)
}

extern "C" void kernel_launch(void* const* d_in, const int* in_sizes, int n_in,
                              void* d_out, int out_size) {
    (void)in_sizes; (void)n_in; (void)out_size;
    const float* hs    = (const float*)d_in[0];
    const float* enc   = (const float*)d_in[1];
    const float* ln1g  = (const float*)d_in[2];
    const float* ln1b  = (const float*)d_in[3];
    const float* Wq1   = (const float*)d_in[4];
    const float* Wk1   = (const float*)d_in[5];
    const float* Wv1   = (const float*)d_in[6];
    const float* Wo1   = (const float*)d_in[7];
    const float* bo1   = (const float*)d_in[8];
    const float* ln2g  = (const float*)d_in[9];
    const float* ln2b  = (const float*)d_in[10];
    const float* Wq2   = (const float*)d_in[11];
    const float* Wk2   = (const float*)d_in[12];
    const float* Wv2   = (const float*)d_in[13];
    const float* Wo2   = (const float*)d_in[14];
    const float* bo2   = (const float*)d_in[15];
    const float* ln3g  = (const float*)d_in[16];
    const float* ln3b  = (const float*)d_in[17];
    const float* Wff1  = (const float*)d_in[18];
    const float* bff1  = (const float*)d_in[19];
    const float* Wff2  = (const float*)d_in[20];
    const float* bff2  = (const float*)d_in[21];
    float* out = (float*)d_out;

    void* p;
    cudaGetSymbolAddress(&p, g_n);    float* n_   = (float*)p;
    cudaGetSymbolAddress(&p, g_q);    float* q_   = (float*)p;
    cudaGetSymbolAddress(&p, g_k);    float* k_   = (float*)p;
    cudaGetSymbolAddress(&p, g_v);    float* v_   = (float*)p;
    cudaGetSymbolAddress(&p, g_attn); float* at_  = (float*)p;
    cudaGetSymbolAddress(&p, g_scores); float* sc_ = (float*)p;
    cudaGetSymbolAddress(&p, g_proj); float* pj_  = (float*)p;
    cudaGetSymbolAddress(&p, g_gg);   float* gg_  = (float*)p;
    TCPtrs tc;
    cudaGetSymbolAddress(&p, g_ah);   tc.ah = (__nv_bfloat16*)p;
    cudaGetSymbolAddress(&p, g_al);   tc.al = (__nv_bfloat16*)p;
    cudaGetSymbolAddress(&p, g_bh);   tc.bh = (__nv_bfloat16*)p;
    cudaGetSymbolAddress(&p, g_bl);   tc.bl = (__nv_bfloat16*)p;
    __nv_bfloat16 *qi_, *ki_, *vi_;
    cudaGetSymbolAddress(&p, g_qi);   qi_ = (__nv_bfloat16*)p;
    cudaGetSymbolAddress(&p, g_ki);   ki_ = (__nv_bfloat16*)p;
    cudaGetSymbolAddress(&p, g_vi);   vi_ = (__nv_bfloat16*)p;

    const float premul = 1.0f / sqrtf((float)HDIM);
    const size_t nQ = (size_t)ROWS * DMODEL;
    const size_t nE = (size_t)ENCROWS * DMODEL;

    // ================= self-attention =================
    ln_kernel<<<ROWS, 256>>>(hs, ln1g, ln1b, n_);
    convert_A(n_, nQ, tc.ah, tc.al);
    trans_W(Wq1, DMODEL, DMODEL, tc.bh, tc.bl);
    tc_gemm(tc, nullptr, nullptr, q_, ROWS, DMODEL, DMODEL);
    trans_W(Wk1, DMODEL, DMODEL, tc.bh, tc.bl);
    tc_gemm(tc, nullptr, nullptr, k_, ROWS, DMODEL, DMODEL);
    trans_W(Wv1, DMODEL, DMODEL, tc.bh, tc.bl);
    tc_gemm(tc, nullptr, nullptr, v_, ROWS, DMODEL, DMODEL);
    init_stats_kernel<<<1, 32>>>();
    minmax_kernel<<<512, 256>>>(q_, nQ, 0);
    minmax_kernel<<<512, 256>>>(k_, nQ, 1);
    minmax_kernel<<<512, 256>>>(v_, nQ, 2);
    quant_qk_kernel<<<dim3(32, BH), 256>>>(q_, qi_, SEQ, 1024, 0);
    quant_qk_kernel<<<dim3(32, BH), 256>>>(k_, ki_, SEQ, 1024, 1);
    quant_v_kernel<<<dim3(8, BH), 256>>>(v_, vi_, SEQ, 1024, 2);
    scores_mma_kernel<<<dim3(8, 8, BH), 256>>>(sc_, SEQ, 1024, premul);
    softmax_norm_kernel<<<NROWSBH, 128>>>(SEQ);
    maxinv_kernel<<<64, 256>>>();
    quantp_kernel<<<NROWSBH, 256>>>(SEQ, 1024);
    pv_mma_kernel<<<dim3(8, BH), 256>>>(1024);
    convert_A(at_, nQ, tc.ah, tc.al);
    trans_W(Wo1, DMODEL, DMODEL, tc.bh, tc.bl);
    tc_gemm(tc, bo1, hs, out, ROWS, DMODEL, DMODEL);

    // ================= cross-attention =================
    ln_kernel<<<ROWS, 256>>>(out, ln2g, ln2b, n_);
    convert_A(n_, nQ, tc.ah, tc.al);
    trans_W(Wq2, DMODEL, DMODEL, tc.bh, tc.bl);
    tc_gemm(tc, nullptr, nullptr, q_, ROWS, DMODEL, DMODEL);
    convert_A(enc, nE, tc.ah, tc.al);
    trans_W(Wk2, DMODEL, DMODEL, tc.bh, tc.bl);
    tc_gemm(tc, nullptr, nullptr, k_, ENCROWS, DMODEL, DMODEL);
    trans_W(Wv2, DMODEL, DMODEL, tc.bh, tc.bl);
    tc_gemm(tc, nullptr, nullptr, v_, ENCROWS, DMODEL, DMODEL);
    init_stats_kernel<<<1, 32>>>();
    minmax_kernel<<<512, 256>>>(q_, nQ, 0);
    minmax_kernel<<<512, 256>>>(k_, nE, 1);
    minmax_kernel<<<512, 256>>>(v_, nE, 2);
    quant_qk_kernel<<<dim3(32, BH), 256>>>(q_, qi_, SEQ, 1024, 0);
    quant_qk_kernel<<<dim3(4, BH), 256>>>(k_, ki_, SENC, 128, 1);
    quant_v_kernel<<<dim3(8, BH), 256>>>(v_, vi_, SENC, 128, 2);
    scores_mma_kernel<<<dim3(1, 8, BH), 256>>>(sc_, SENC, 128, premul);
    softmax_norm_kernel<<<NROWSBH, 128>>>(SENC);
    maxinv_kernel<<<64, 256>>>();
    quantp_kernel<<<NROWSBH, 256>>>(SENC, 128);
    pv_mma_kernel<<<dim3(8, BH), 256>>>(128);
    convert_A(at_, nQ, tc.ah, tc.al);
    trans_W(Wo2, DMODEL, DMODEL, tc.bh, tc.bl);
    tc_gemm(tc, bo2, out, out, ROWS, DMODEL, DMODEL);

    // ================= feed-forward (GEGLU) =================
    ln_kernel<<<ROWS, 256>>>(out, ln3g, ln3b, n_);
    convert_A(n_, nQ, tc.ah, tc.al);
    trans_W(Wff1, DMODEL, 2 * FFD, tc.bh, tc.bl);
    tc_gemm(tc, bff1, nullptr, pj_, ROWS, 2 * FFD, DMODEL);
    geglu_kernel<<<8192, 256>>>();
    convert_A(gg_, (size_t)ROWS * FFD, tc.ah, tc.al);
    trans_W(Wff2, FFD, DMODEL, tc.bh, tc.bl);
    tc_gemm(tc, bff2, out, out, ROWS, DMODEL, FFD);
}

// round 7
// speedup vs baseline: 2.5202x; 1.0013x over previous
#include <cuda_runtime.h>
#include <cuda_bf16.h>
#include <math.h>
#include <stdint.h>

// Problem dims
#define BATCH   8
#define SEQ     1024
#define DMODEL  1152
#define NHEAD   16
#define HDIM    72
#define SENC    77
#define FFD     4608
#define ROWS    (BATCH*SEQ)        // 8192
#define ENCROWS (BATCH*SENC)       // 616
#define BH      (BATCH*NHEAD)      // 128
#define NROWSBH (BH*SEQ)           // 131072

__device__ __forceinline__ uint32_t smem_to_u32(const void* smem_ptr) {
    uint32_t addr;
    asm("{ .reg .u64 tmp; cvta.to.shared.u64 tmp, %1; cvt.u32.u64 %0, tmp; }"
        : "=r"(addr) : "l"(smem_ptr));
    return addr;
}

// fast exp on the FMA pipe (no MUFU). x <= 0 expected; rel err ~2e-7.
__device__ __forceinline__ float fexp(float x) {
    float t = x * 1.4426950408889634f;
    t = fmaxf(t, -126.0f);
    float fi = floorf(t);
    float f = t - fi;
    float p = 1.3333558146e-3f;
    p = fmaf(p, f, 9.6181291076e-3f);
    p = fmaf(p, f, 5.5504108664e-2f);
    p = fmaf(p, f, 2.4022650695910e-1f);
    p = fmaf(p, f, 6.9314718055994e-1f);
    p = fmaf(p, f, 1.0f);
    return p * __int_as_float(((int)fi + 127) << 23);
}

__device__ __forceinline__ void split_store(
    __nv_bfloat16* __restrict__ h, __nv_bfloat16* __restrict__ l,
    size_t idx, float v)
{
    __nv_bfloat16 hh = __float2bfloat16(v);
    h[idx] = hh;
    l[idx] = __float2bfloat16(v - __bfloat162float(hh));
}

// ----------------------- scratch (device globals; no runtime alloc) ---------
__device__ float g_q[(size_t)ROWS*DMODEL];
__device__ float g_k[(size_t)ROWS*DMODEL];
__device__ float g_v[(size_t)ROWS*DMODEL];
__device__ float g_scores[(size_t)BH*SEQ*SEQ];       // fp32 scores
__device__ float g_rowM[NROWSBH];
__device__ float g_rowInvZ[NROWSBH];
__device__ float g_proj[(size_t)ROWS*2*FFD];
__device__ float g_stats[8];
// bf16 hi/lo operand buffers (weight GEMMs)
__device__ __nv_bfloat16 g_ah[(size_t)ROWS*FFD];
__device__ __nv_bfloat16 g_al[(size_t)ROWS*FFD];
__device__ __nv_bfloat16 g_bh[(size_t)(2*FFD)*DMODEL];
__device__ __nv_bfloat16 g_bl[(size_t)(2*FFD)*DMODEL];
// integer-bf16 attention operands
__device__ __nv_bfloat16 g_qi[(size_t)BH*1024*80];
__device__ __nv_bfloat16 g_ki[(size_t)BH*1024*80];
__device__ __nv_bfloat16 g_vi[(size_t)BH*128*1024];
__device__ __nv_bfloat16 g_pi[(size_t)NROWSBH*1024];

// ----------------------- atomic float min/max -------------------------------
__device__ __forceinline__ void atomicMaxF(float* a, float v) {
    if (v >= 0.f) atomicMax((int*)a, __float_as_int(v));
    else          atomicMin((unsigned int*)a, __float_as_uint(v));
}
__device__ __forceinline__ void atomicMinF(float* a, float v) {
    if (v >= 0.f) atomicMin((int*)a, __float_as_int(v));
    else          atomicMax((unsigned int*)a, __float_as_uint(v));
}

// ----------------------- LayerNorm -> bf16 hi/lo -----------------------------
__global__ __launch_bounds__(256) void ln_split_kernel(
    const float* __restrict__ x, const float* __restrict__ g,
    const float* __restrict__ b,
    __nv_bfloat16* __restrict__ oh, __nv_bfloat16* __restrict__ ol)
{
    const int N = DMODEL;
    size_t row = blockIdx.x;
    const float* xr = x + row * N;
    int tid = threadIdx.x;

    float lv[5];
    int cnt = 0;
    float s = 0.f;
    for (int i = tid; i < N; i += 256) { float t = xr[i]; lv[cnt++] = t; s += t; }

    __shared__ float sh[8];
    for (int ofs = 16; ofs; ofs >>= 1) s += __shfl_xor_sync(0xffffffffu, s, ofs);
    if ((tid & 31) == 0) sh[tid >> 5] = s;
    __syncthreads();
    float tot = 0.f;
    #pragma unroll
    for (int i = 0; i < 8; i++) tot += sh[i];
    float mu = tot * (1.f / (float)N);

    float vs = 0.f;
    for (int c = 0; c < cnt; c++) { float d = lv[c] - mu; vs += d * d; }
    __syncthreads();
    for (int ofs = 16; ofs; ofs >>= 1) vs += __shfl_xor_sync(0xffffffffu, vs, ofs);
    if ((tid & 31) == 0) sh[tid >> 5] = vs;
    __syncthreads();
    float vtot = 0.f;
    #pragma unroll
    for (int i = 0; i < 8; i++) vtot += sh[i];
    float inv = rsqrtf(vtot * (1.f / (float)N) + 1e-5f);

    int i = tid;
    for (int c = 0; c < cnt; c++, i += 256) {
        float val = (lv[c] - mu) * inv * g[i] + b[i];
        split_store(oh, ol, row * N + i, val);
    }
}

// ----------------------- fp32 -> bf16 hi/lo split (for enc) -----------------
__global__ __launch_bounds__(256) void convert_split_kernel(
    const float* __restrict__ x, size_t n4,
    __nv_bfloat16* __restrict__ h, __nv_bfloat16* __restrict__ l)
{
    for (size_t i = (size_t)blockIdx.x * blockDim.x + threadIdx.x; i < n4;
         i += (size_t)gridDim.x * blockDim.x) {
        float4 v = ((const float4*)x)[i];
        __nv_bfloat16 h0 = __float2bfloat16(v.x);
        __nv_bfloat16 h1 = __float2bfloat16(v.y);
        __nv_bfloat16 h2 = __float2bfloat16(v.z);
        __nv_bfloat16 h3 = __float2bfloat16(v.w);
        __nv_bfloat162* hp = (__nv_bfloat162*)h;
        __nv_bfloat162* lp = (__nv_bfloat162*)l;
        hp[2*i]   = __nv_bfloat162(h0, h1);
        hp[2*i+1] = __nv_bfloat162(h2, h3);
        lp[2*i]   = __nv_bfloat162(__float2bfloat16(v.x - __bfloat162float(h0)),
                                   __float2bfloat16(v.y - __bfloat162float(h1)));
        lp[2*i+1] = __nv_bfloat162(__float2bfloat16(v.z - __bfloat162float(h2)),
                                   __float2bfloat16(v.w - __bfloat162float(h3)));
    }
}

// ----------------------- weight transpose + hi/lo split ----------------------
__global__ __launch_bounds__(256) void wt_trans_split_kernel(
    const float* __restrict__ W, int K, int N,
    __nv_bfloat16* __restrict__ Th, __nv_bfloat16* __restrict__ Tl)
{
    __shared__ float tile[32][33];
    int n0 = blockIdx.x * 32, k0 = blockIdx.y * 32;
    int tx = threadIdx.x & 31, ty = threadIdx.x >> 5;
    #pragma unroll
    for (int r = ty; r < 32; r += 8) {
        int k = k0 + r, n = n0 + tx;
        tile[r][tx] = (k < K && n < N) ? W[(size_t)k * N + n] : 0.f;
    }
    __syncthreads();
    #pragma unroll
    for (int r = ty; r < 32; r += 8) {
        int n = n0 + r, k = k0 + tx;
        if (n < N && k < K) {
            float x = tile[tx][r];
            __nv_bfloat16 hh = __float2bfloat16(x);
            Th[(size_t)n * K + k] = hh;
            Tl[(size_t)n * K + k] = __float2bfloat16(x - __bfloat162float(hh));
        }
    }
}

// ----------------------- mma primitives -------------------------------------
__device__ __forceinline__ void cp16(uint32_t dst, const void* src, uint32_t sz) {
    asm volatile("cp.async.cg.shared.global [%0], [%1], 16, %2;"
                 :: "r"(dst), "l"(src), "r"(sz) : "memory");
}
template<int NN> __device__ __forceinline__ void cpasync_wait() {
    asm volatile("cp.async.wait_group %0;" :: "n"(NN) : "memory");
}
__device__ __forceinline__ void ldsm_x4(uint32_t* r, uint32_t addr) {
    asm volatile("ldmatrix.sync.aligned.m8n8.x4.shared.b16 {%0,%1,%2,%3}, [%4];"
        : "=r"(r[0]), "=r"(r[1]), "=r"(r[2]), "=r"(r[3]) : "r"(addr));
}
__device__ __forceinline__ void mma_bf16(float* c, const uint32_t* a, const uint32_t* b) {
    asm volatile("mma.sync.aligned.m16n8k16.row.col.f32.bf16.bf16.f32 "
        "{%0,%1,%2,%3}, {%4,%5,%6,%7}, {%8,%9}, {%0,%1,%2,%3};"
        : "+f"(c[0]), "+f"(c[1]), "+f"(c[2]), "+f"(c[3])
        : "r"(a[0]), "r"(a[1]), "r"(a[2]), "r"(a[3]), "r"(b[0]), "r"(b[1]));
}

// ----------------------- mma.sync bf16x3 GEMM (2-stage, 2 CTAs/SM) ----------
#define TC_STAGE_BYTES 40960
#define TC_SMEM_TOTAL  (2*TC_STAGE_BYTES)

__device__ __forceinline__ void tc_load_stage(
    uint32_t sbase,
    const __nv_bfloat16* __restrict__ Ah, const __nv_bfloat16* __restrict__ Al,
    const __nv_bfloat16* __restrict__ Bh, const __nv_bfloat16* __restrict__ Bl,
    int m0, int M, int n0, int K, int k0, int tid)
{
    #pragma unroll
    for (int i = 0; i < 2; i++) {
        int c = tid + i * 256;
        int row = c >> 2, kc = c & 3;
        uint32_t soff = (uint32_t)(row * 80 + kc * 16);
        size_t goffA = (size_t)(m0 + row) * K + k0 + kc * 8;
        uint32_t szA = ((m0 + row) < M) ? 16u : 0u;
        cp16(sbase + soff,         Ah + goffA, szA);
        cp16(sbase + 10240 + soff, Al + goffA, szA);
        size_t goffB = (size_t)(n0 + row) * K + k0 + kc * 8;
        cp16(sbase + 20480 + soff, Bh + goffB, 16u);
        cp16(sbase + 30720 + soff, Bl + goffB, 16u);
    }
    asm volatile("cp.async.commit_group;" ::: "memory");
}

__global__ __launch_bounds__(256, 2) void tc_gemm_kernel(
    const __nv_bfloat16* __restrict__ Ah, const __nv_bfloat16* __restrict__ Al,
    const __nv_bfloat16* __restrict__ Bh, const __nv_bfloat16* __restrict__ Bl,
    const float* __restrict__ bias, const float* __restrict__ res,
    float* __restrict__ C, int M, int N, int K)
{
    extern __shared__ char smem[];
    uint32_t sb = smem_to_u32(smem);
    int tid = threadIdx.x;
    int wid = tid >> 5, lane = tid & 31;
    int n0 = blockIdx.x * 128, m0 = blockIdx.y * 128;
    int wm = wid & 3, wn = wid >> 2;

    float acc[2][8][4];
    #pragma unroll
    for (int mt = 0; mt < 2; mt++)
        #pragma unroll
        for (int nt = 0; nt < 8; nt++)
            #pragma unroll
            for (int e = 0; e < 4; e++) acc[mt][nt][e] = 0.f;

    const int KT = K >> 5;

    tc_load_stage(sb, Ah, Al, Bh, Bl, m0, M, n0, K, 0, tid);

    for (int t = 0; t < KT; t++) {
        if (t + 1 < KT) {
            tc_load_stage(sb + ((t + 1) & 1) * TC_STAGE_BYTES,
                          Ah, Al, Bh, Bl, m0, M, n0, K, (t + 1) << 5, tid);
            cpasync_wait<1>();
        } else {
            cpasync_wait<0>();
        }
        __syncthreads();

        uint32_t base = sb + (t & 1) * TC_STAGE_BYTES;
        #pragma unroll
        for (int kk = 0; kk < 2; kk++) {
            uint32_t ah[2][4], al[2][4];
            #pragma unroll
            for (int mt = 0; mt < 2; mt++) {
                uint32_t arow = (uint32_t)(wm * 32 + mt * 16 + (lane & 15));
                uint32_t abyte = arow * 80 + kk * 32 + ((lane >> 4) << 4);
                ldsm_x4(ah[mt], base + abyte);
                ldsm_x4(al[mt], base + 10240 + abyte);
            }
            #pragma unroll
            for (int bp = 0; bp < 4; bp++) {
                uint32_t brow = (uint32_t)(wn * 64 + bp * 16 + (lane & 7) + (((lane >> 4) & 1) << 3));
                uint32_t bbyte = brow * 80 + kk * 32 + (((lane >> 3) & 1) << 4);
                uint32_t bh4[4], bl4[4];
                ldsm_x4(bh4, base + 20480 + bbyte);
                ldsm_x4(bl4, base + 30720 + bbyte);
                // pass-major order: same-acc MMAs spaced by 4 independents (breaks RAW stalls)
                #pragma unroll
                for (int sub = 0; sub < 2; sub++)
                    #pragma unroll
                    for (int mt = 0; mt < 2; mt++)
                        mma_bf16(acc[mt][bp * 2 + sub], ah[mt], bh4 + sub * 2);
                #pragma unroll
                for (int sub = 0; sub < 2; sub++)
                    #pragma unroll
                    for (int mt = 0; mt < 2; mt++)
                        mma_bf16(acc[mt][bp * 2 + sub], ah[mt], bl4 + sub * 2);
                #pragma unroll
                for (int sub = 0; sub < 2; sub++)
                    #pragma unroll
                    for (int mt = 0; mt < 2; mt++)
                        mma_bf16(acc[mt][bp * 2 + sub], al[mt], bh4 + sub * 2);
            }
        }
        __syncthreads();
    }

    #pragma unroll
    for (int mt = 0; mt < 2; mt++) {
        int r0 = m0 + wm * 32 + mt * 16 + (lane >> 2);
        #pragma unroll
        for (int nt = 0; nt < 8; nt++) {
            int cc = n0 + wn * 64 + nt * 8 + (lane & 3) * 2;
            #pragma unroll
            for (int h = 0; h < 2; h++) {
                int r = r0 + h * 8;
                if (r >= M) continue;
                float2 o = make_float2(acc[mt][nt][h * 2], acc[mt][nt][h * 2 + 1]);
                if (bias) {
                    float2 bb = *(const float2*)(bias + cc);
                    o.x += bb.x; o.y += bb.y;
                }
                if (res) {
                    float2 rv = *(const float2*)(res + (size_t)r * N + cc);
                    o.x += rv.x; o.y += rv.y;
                }
                *(float2*)(C + (size_t)r * N + cc) = o;
            }
        }
    }
}

// ----------------------- stats init / minmax --------------------------------
__global__ void init_stats_kernel() {
    int t = threadIdx.x;
    if (t < 3) { g_stats[2 * t] = INFINITY; g_stats[2 * t + 1] = -INFINITY; }
    if (t == 3) g_stats[6] = 0.f;
}

__global__ __launch_bounds__(256) void minmax_kernel(const float* __restrict__ x, size_t n, int slot) {
    float mn = INFINITY, mx = -INFINITY;
    for (size_t i = (size_t)blockIdx.x * blockDim.x + threadIdx.x; i < n;
         i += (size_t)gridDim.x * blockDim.x) {
        float v = x[i];
        mn = fminf(mn, v);
        mx = fmaxf(mx, v);
    }
    __shared__ float smn[8], smx[8];
    int tid = threadIdx.x;
    for (int o = 16; o; o >>= 1) {
        mn = fminf(mn, __shfl_xor_sync(0xffffffffu, mn, o));
        mx = fmaxf(mx, __shfl_xor_sync(0xffffffffu, mx, o));
    }
    if ((tid & 31) == 0) { smn[tid >> 5] = mn; smx[tid >> 5] = mx; }
    __syncthreads();
    if (tid == 0) {
        for (int i = 1; i < 8; i++) { mn = fminf(mn, smn[i]); mx = fmaxf(mx, smx[i]); }
        atomicMinF(&g_stats[2 * slot], mn);
        atomicMaxF(&g_stats[2 * slot + 1], mx);
    }
}

// ----------------------- quantize to integer-bf16 ----------------------------
__global__ __launch_bounds__(256) void quant_qk_kernel(
    const float* __restrict__ x, __nv_bfloat16* __restrict__ out,
    int S, int SPAD, int slot)
{
    int bh = blockIdx.y, s0 = blockIdx.x * 32;
    int b = bh >> 4, h = bh & 15;
    float mn = g_stats[2 * slot], mx = g_stats[2 * slot + 1];
    float delta = (mx - mn) * (1.f / 255.f);
    float zp = rintf(-mn / delta);
    #pragma unroll
    for (int it = 0; it < 10; it++) {
        int local = threadIdx.x + it * 256;
        int sl = local / 80, d = local % 80;
        int s = s0 + sl;
        float val = 0.f;
        if (d < 72 && s < S) {
            float xv = x[((size_t)b * S + s) * DMODEL + h * HDIM + d];
            float q = fminf(fmaxf(rintf(xv / delta) + zp, 0.f), 255.f);
            val = q - zp;
        }
        out[((size_t)bh * SPAD + s) * 80 + d] = __float2bfloat16(val);
    }
}

__global__ __launch_bounds__(256) void quant_v_kernel(
    const float* __restrict__ x, __nv_bfloat16* __restrict__ out,
    int S, int SPAD, int slot)
{
    int bh = blockIdx.y;
    int b = bh >> 4, h = bh & 15;
    int schunk = SPAD >> 3;
    int sbase = blockIdx.x * schunk;
    float mn = g_stats[2 * slot], mx = g_stats[2 * slot + 1];
    float delta = (mx - mn) * (1.f / 255.f);
    float zp = rintf(-mn / delta);
    for (int d = 0; d < 128; d++) {
        const float* src = x + ((size_t)b * S) * DMODEL + h * HDIM + d;
        __nv_bfloat16* dst = out + ((size_t)bh * 128 + d) * SPAD;
        for (int s = sbase + threadIdx.x; s < sbase + schunk; s += 256) {
            float val = 0.f;
            if (d < 72 && s < S) {
                float xv = src[(size_t)s * DMODEL];
                float q = fminf(fmaxf(rintf(xv / delta) + zp, 0.f), 255.f);
                val = q - zp;
            }
            dst[s] = __float2bfloat16(val);
        }
    }
}

// ----------------------- scores = premul*dq*dk * Iq @ Ik^T (bf16 MMA) -------
__global__ __launch_bounds__(256) void scores_mma_kernel(
    float* __restrict__ scores, int SK, int KROWS, float premul)
{
    __shared__ char sA[128 * 176];
    __shared__ char sB[128 * 176];
    int tid = threadIdx.x, wid = tid >> 5, lane = tid & 31;
    int bh = blockIdx.z;
    int kcol0 = blockIdx.x * 128, qrow0 = blockIdx.y * 128;
    int wm = wid & 3, wn = wid >> 2;
    uint32_t sa = smem_to_u32(sA), sb = smem_to_u32(sB);

    const __nv_bfloat16* qb = g_qi + ((size_t)bh * 1024 + qrow0) * 80;
    const __nv_bfloat16* kb = g_ki + ((size_t)bh * KROWS + kcol0) * 80;
    #pragma unroll
    for (int i = 0; i < 5; i++) {
        int c = tid + i * 256;
        int row = c / 10, j = c - row * 10;
        cp16(sa + row * 176 + j * 16, qb + (size_t)row * 80 + j * 8, 16u);
        cp16(sb + row * 176 + j * 16, kb + (size_t)row * 80 + j * 8, 16u);
    }
    asm volatile("cp.async.commit_group;" ::: "memory");
    cpasync_wait<0>();
    __syncthreads();

    float acc[2][8][4];
    #pragma unroll
    for (int mt = 0; mt < 2; mt++)
        #pragma unroll
        for (int nt = 0; nt < 8; nt++)
            #pragma unroll
            for (int e = 0; e < 4; e++) acc[mt][nt][e] = 0.f;

    #pragma unroll
    for (int kk = 0; kk < 5; kk++) {
        uint32_t af[2][4];
        #pragma unroll
        for (int mt = 0; mt < 2; mt++) {
            uint32_t arow = (uint32_t)(wm * 32 + mt * 16 + (lane & 15));
            ldsm_x4(af[mt], sa + arow * 176 + kk * 32 + ((lane >> 4) << 4));
        }
        #pragma unroll
        for (int bp = 0; bp < 4; bp++) {
            uint32_t brow = (uint32_t)(wn * 64 + bp * 16 + (lane & 7) + (((lane >> 4) & 1) << 3));
            uint32_t bf4[4];
            ldsm_x4(bf4, sb + brow * 176 + kk * 32 + (((lane >> 3) & 1) << 4));
            #pragma unroll
            for (int sub = 0; sub < 2; sub++) {
                int nt = bp * 2 + sub;
                #pragma unroll
                for (int mt = 0; mt < 2; mt++)
                    mma_bf16(acc[mt][nt], af[mt], bf4 + sub * 2);
            }
        }
    }

    float dq = (g_stats[1] - g_stats[0]) * (1.f / 255.f);
    float dk = (g_stats[3] - g_stats[2]) * (1.f / 255.f);
    float sc = dq * dk * premul;

    #pragma unroll
    for (int mt = 0; mt < 2; mt++) {
        int r0 = qrow0 + wm * 32 + mt * 16 + (lane >> 2);
        #pragma unroll
        for (int nt = 0; nt < 8; nt++) {
            int c0 = kcol0 + wn * 64 + nt * 8 + (lane & 3) * 2;
            #pragma unroll
            for (int h = 0; h < 2; h++) {
                int r = r0 + h * 8;
                size_t base = ((size_t)bh * SEQ + r) * SK;
                if (c0 < SK)     scores[base + c0]     = acc[mt][nt][h * 2]     * sc;
                if (c0 + 1 < SK) scores[base + c0 + 1] = acc[mt][nt][h * 2 + 1] * sc;
            }
        }
    }
}

// ----------------------- softmax stats (no write-back) ----------------------
__global__ __launch_bounds__(128) void softmax_stats_kernel(int SK) {
    size_t row = blockIdx.x;
    const float* sr = g_scores + row * (size_t)SK;
    int tid = threadIdx.x;
    float vals[8];
    int cnt = 0;
    float m = -INFINITY;
    for (int i = tid; i < SK; i += 128) { float t = sr[i]; vals[cnt++] = t; m = fmaxf(m, t); }

    __shared__ float sh[4];
    for (int o = 16; o; o >>= 1) m = fmaxf(m, __shfl_xor_sync(0xffffffffu, m, o));
    if ((tid & 31) == 0) sh[tid >> 5] = m;
    __syncthreads();
    m = fmaxf(fmaxf(sh[0], sh[1]), fmaxf(sh[2], sh[3]));

    float z = 0.f;
    for (int c = 0; c < cnt; c++) z += fexp(vals[c] - m);
    __syncthreads();
    for (int o = 16; o; o >>= 1) z += __shfl_xor_sync(0xffffffffu, z, o);
    __shared__ float sh2[4];
    if ((tid & 31) == 0) sh2[tid >> 5] = z;
    __syncthreads();
    if (tid == 0) {
        g_rowM[row] = m;
        g_rowInvZ[row] = 1.f / (sh2[0] + sh2[1] + sh2[2] + sh2[3]);
    }
}

__global__ __launch_bounds__(256) void maxinv_kernel() {
    float m = 0.f;
    for (int i = blockIdx.x * blockDim.x + threadIdx.x; i < NROWSBH;
         i += gridDim.x * blockDim.x)
        m = fmaxf(m, g_rowInvZ[i]);
    __shared__ float sh[8];
    int tid = threadIdx.x;
    for (int o = 16; o; o >>= 1) m = fmaxf(m, __shfl_xor_sync(0xffffffffu, m, o));
    if ((tid & 31) == 0) sh[tid >> 5] = m;
    __syncthreads();
    if (tid == 0) {
        for (int i = 1; i < 8; i++) m = fmaxf(m, sh[i]);
        atomicMaxF(&g_stats[6], m);
    }
}

// ----------------------- quantize probs (recompute exp, write bf16) ---------
__global__ __launch_bounds__(256) void quantp_kernel(int SK, int SKPAD) {
    size_t row = blockIdx.x;
    float m = g_rowM[row];
    float scale = g_rowInvZ[row] * (255.f / g_stats[6]);
    const float* src = g_scores + row * (size_t)SK;
    __nv_bfloat16* dst = g_pi + row * (size_t)SKPAD;
    for (int kc = threadIdx.x; kc < SKPAD; kc += 256) {
        float val = 0.f;
        if (kc < SK) val = fminf(rintf(fexp(src[kc] - m) * scale), 255.f);
        dst[kc] = __float2bfloat16(val);
    }
}

// ----------------------- out = dp*dv * Ip @ Iv^T -> bf16 hi/lo --------------
__global__ __launch_bounds__(256) void pv_mma_kernel(
    __nv_bfloat16* __restrict__ oh, __nv_bfloat16* __restrict__ ol, int SKPAD)
{
    __shared__ char smem2[2][20480];
    int tid = threadIdx.x, wid = tid >> 5, lane = tid & 31;
    int bh = blockIdx.y, m0 = blockIdx.x * 128;
    int b = bh >> 4, h = bh & 15;
    int wm = wid & 3, wn = wid >> 2;
    uint32_t s0 = smem_to_u32(smem2);

    const __nv_bfloat16* pb = g_pi + ((size_t)bh * SEQ + m0) * SKPAD;
    const __nv_bfloat16* vb = g_vi + (size_t)bh * 128 * SKPAD;
    const int KT = SKPAD >> 5;

    float acc[2][8][4];
    #pragma unroll
    for (int mt = 0; mt < 2; mt++)
        #pragma unroll
        for (int nt = 0; nt < 8; nt++)
            #pragma unroll
            for (int e = 0; e < 4; e++) acc[mt][nt][e] = 0.f;

    {
        #pragma unroll
        for (int i = 0; i < 2; i++) {
            int c = tid + i * 256;
            int row = c >> 2, j = c & 3;
            cp16(s0 + row * 80 + j * 16,         pb + (size_t)row * SKPAD + j * 8, 16u);
            cp16(s0 + 10240 + row * 80 + j * 16, vb + (size_t)row * SKPAD + j * 8, 16u);
        }
        asm volatile("cp.async.commit_group;" ::: "memory");
    }

    for (int t = 0; t < KT; t++) {
        if (t + 1 < KT) {
            uint32_t sn = s0 + ((t + 1) & 1) * 20480;
            int k0 = (t + 1) << 5;
            #pragma unroll
            for (int i = 0; i < 2; i++) {
                int c = tid + i * 256;
                int row = c >> 2, j = c & 3;
                cp16(sn + row * 80 + j * 16,         pb + (size_t)row * SKPAD + k0 + j * 8, 16u);
                cp16(sn + 10240 + row * 80 + j * 16, vb + (size_t)row * SKPAD + k0 + j * 8, 16u);
            }
            asm volatile("cp.async.commit_group;" ::: "memory");
            cpasync_wait<1>();
        } else {
            cpasync_wait<0>();
        }
        __syncthreads();

        uint32_t base = s0 + (t & 1) * 20480;
        #pragma unroll
        for (int kk = 0; kk < 2; kk++) {
            uint32_t af[2][4];
            #pragma unroll
            for (int mt = 0; mt < 2; mt++) {
                uint32_t arow = (uint32_t)(wm * 32 + mt * 16 + (lane & 15));
                ldsm_x4(af[mt], base + arow * 80 + kk * 32 + ((lane >> 4) << 4));
            }
            int bplim = (wn == 0) ? 4 : 1;
            for (int bp = 0; bp < bplim; bp++) {
                uint32_t brow = (uint32_t)(wn * 64 + bp * 16 + (lane & 7) + (((lane >> 4) & 1) << 3));
                uint32_t bf4[4];
                ldsm_x4(bf4, base + 10240 + brow * 80 + kk * 32 + (((lane >> 3) & 1) << 4));
                #pragma unroll
                for (int sub = 0; sub < 2; sub++) {
                    int nt = bp * 2 + sub;
                    #pragma unroll
                    for (int mt = 0; mt < 2; mt++)
                        mma_bf16(acc[mt][nt], af[mt], bf4 + sub * 2);
                }
            }
        }
        __syncthreads();
    }

    float dp = g_stats[6] * (1.f / 255.f);
    float dv = (g_stats[5] - g_stats[4]) * (1.f / 255.f);
    float sc = dp * dv;

    #pragma unroll
    for (int mt = 0; mt < 2; mt++) {
        int r0 = m0 + wm * 32 + mt * 16 + (lane >> 2);
        #pragma unroll
        for (int nt = 0; nt < 8; nt++) {
            int n = wn * 64 + nt * 8 + (lane & 3) * 2;
            if (n >= 72) continue;
            #pragma unroll
            for (int h2 = 0; h2 < 2; h2++) {
                int r = r0 + h2 * 8;
                size_t idx = ((size_t)b * SEQ + r) * DMODEL + h * HDIM + n;
                split_store(oh, ol, idx,     acc[mt][nt][h2 * 2]     * sc);
                split_store(oh, ol, idx + 1, acc[mt][nt][h2 * 2 + 1] * sc);
            }
        }
    }
}

// ----------------------- GEGLU -> bf16 hi/lo --------------------------------
__global__ __launch_bounds__(256) void geglu_split_kernel(
    __nv_bfloat16* __restrict__ oh, __nv_bfloat16* __restrict__ ol)
{
    size_t n = (size_t)ROWS * FFD;
    for (size_t idx = (size_t)blockIdx.x * blockDim.x + threadIdx.x; idx < n;
         idx += (size_t)gridDim.x * blockDim.x) {
        size_t row = idx / FFD;
        int c = (int)(idx % FFD);
        float a  = g_proj[row * (2 * FFD) + c];
        float gt = g_proj[row * (2 * FFD) + FFD + c];
        float gl = 0.5f * gt * (1.f + erff(gt * 0.70710678118654752440f));
        split_store(oh, ol, idx, a * gl);
    }
}

// ----------------------- host orchestration ---------------------------------
struct TCPtrs {
    __nv_bfloat16 *ah, *al, *bh, *bl;
};

static void tc_gemm(const TCPtrs& p, const float* bias, const float* res,
                    float* C, int M, int N, int K) {
    static bool attr_set = false;
    if (!attr_set) {
        cudaFuncSetAttribute(tc_gemm_kernel, cudaFuncAttributeMaxDynamicSharedMemorySize,
                             TC_SMEM_TOTAL);
        attr_set = true;
    }
    dim3 grid(N / 128, (M + 127) / 128);
    tc_gemm_kernel<<<grid, 256, TC_SMEM_TOTAL>>>(p.ah, p.al, p.bh, p.bl,
                                                 bias, res, C, M, N, K);
}

static void trans_W(const float* W, int K, int N, __nv_bfloat16* Th, __nv_bfloat16* Tl) {
    wt_trans_split_kernel<<<dim3(N / 32, K / 32), 256>>>(W, K, N, Th, Tl);
}

extern "C" void kernel_launch(void* const* d_in, const int* in_sizes, int n_in,
                              void* d_out, int out_size) {
    (void)in_sizes; (void)n_in; (void)out_size;
    const float* hs    = (const float*)d_in[0];
    const float* enc   = (const float*)d_in[1];
    const float* ln1g  = (const float*)d_in[2];
    const float* ln1b  = (const float*)d_in[3];
    const float* Wq1   = (const float*)d_in[4];
    const float* Wk1   = (const float*)d_in[5];
    const float* Wv1   = (const float*)d_in[6];
    const float* Wo1   = (const float*)d_in[7];
    const float* bo1   = (const float*)d_in[8];
    const float* ln2g  = (const float*)d_in[9];
    const float* ln2b  = (const float*)d_in[10];
    const float* Wq2   = (const float*)d_in[11];
    const float* Wk2   = (const float*)d_in[12];
    const float* Wv2   = (const float*)d_in[13];
    const float* Wo2   = (const float*)d_in[14];
    const float* bo2   = (const float*)d_in[15];
    const float* ln3g  = (const float*)d_in[16];
    const float* ln3b  = (const float*)d_in[17];
    const float* Wff1  = (const float*)d_in[18];
    const float* bff1  = (const float*)d_in[19];
    const float* Wff2  = (const float*)d_in[20];
    const float* bff2  = (const float*)d_in[21];
    float* out = (float*)d_out;

    void* p;
    cudaGetSymbolAddress(&p, g_q);      float* q_  = (float*)p;
    cudaGetSymbolAddress(&p, g_k);      float* k_  = (float*)p;
    cudaGetSymbolAddress(&p, g_v);      float* v_  = (float*)p;
    cudaGetSymbolAddress(&p, g_scores); float* sc_ = (float*)p;
    cudaGetSymbolAddress(&p, g_proj);   float* pj_ = (float*)p;
    TCPtrs tc;
    cudaGetSymbolAddress(&p, g_ah);   tc.ah = (__nv_bfloat16*)p;
    cudaGetSymbolAddress(&p, g_al);   tc.al = (__nv_bfloat16*)p;
    cudaGetSymbolAddress(&p, g_bh);   tc.bh = (__nv_bfloat16*)p;
    cudaGetSymbolAddress(&p, g_bl);   tc.bl = (__nv_bfloat16*)p;
    __nv_bfloat16 *qi_, *ki_, *vi_;
    cudaGetSymbolAddress(&p, g_qi);   qi_ = (__nv_bfloat16*)p;
    cudaGetSymbolAddress(&p, g_ki);   ki_ = (__nv_bfloat16*)p;
    cudaGetSymbolAddress(&p, g_vi);   vi_ = (__nv_bfloat16*)p;

    const float premul = 1.0f / sqrtf((float)HDIM);
    const size_t nQ = (size_t)ROWS * DMODEL;
    const size_t nE = (size_t)ENCROWS * DMODEL;

    // ================= self-attention =================
    ln_split_kernel<<<ROWS, 256>>>(hs, ln1g, ln1b, tc.ah, tc.al);
    trans_W(Wq1, DMODEL, DMODEL, tc.bh, tc.bl);
    tc_gemm(tc, nullptr, nullptr, q_, ROWS, DMODEL, DMODEL);
    trans_W(Wk1, DMODEL, DMODEL, tc.bh, tc.bl);
    tc_gemm(tc, nullptr, nullptr, k_, ROWS, DMODEL, DMODEL);
    trans_W(Wv1, DMODEL, DMODEL, tc.bh, tc.bl);
    tc_gemm(tc, nullptr, nullptr, v_, ROWS, DMODEL, DMODEL);
    init_stats_kernel<<<1, 32>>>();
    minmax_kernel<<<512, 256>>>(q_, nQ, 0);
    minmax_kernel<<<512, 256>>>(k_, nQ, 1);
    minmax_kernel<<<512, 256>>>(v_, nQ, 2);
    quant_qk_kernel<<<dim3(32, BH), 256>>>(q_, qi_, SEQ, 1024, 0);
    quant_qk_kernel<<<dim3(32, BH), 256>>>(k_, ki_, SEQ, 1024, 1);
    quant_v_kernel<<<dim3(8, BH), 256>>>(v_, vi_, SEQ, 1024, 2);
    scores_mma_kernel<<<dim3(8, 8, BH), 256>>>(sc_, SEQ, 1024, premul);
    softmax_stats_kernel<<<NROWSBH, 128>>>(SEQ);
    maxinv_kernel<<<64, 256>>>();
    quantp_kernel<<<NROWSBH, 256>>>(SEQ, 1024);
    pv_mma_kernel<<<dim3(8, BH), 256>>>(tc.ah, tc.al, 1024);
    trans_W(Wo1, DMODEL, DMODEL, tc.bh, tc.bl);
    tc_gemm(tc, bo1, hs, out, ROWS, DMODEL, DMODEL);

    // ================= cross-attention =================
    ln_split_kernel<<<ROWS, 256>>>(out, ln2g, ln2b, tc.ah, tc.al);
    trans_W(Wq2, DMODEL, DMODEL, tc.bh, tc.bl);
    tc_gemm(tc, nullptr, nullptr, q_, ROWS, DMODEL, DMODEL);
    convert_split_kernel<<<2048, 256>>>(enc, nE / 4, tc.ah, tc.al);
    trans_W(Wk2, DMODEL, DMODEL, tc.bh, tc.bl);
    tc_gemm(tc, nullptr, nullptr, k_, ENCROWS, DMODEL, DMODEL);
    trans_W(Wv2, DMODEL, DMODEL, tc.bh, tc.bl);
    tc_gemm(tc, nullptr, nullptr, v_, ENCROWS, DMODEL, DMODEL);
    init_stats_kernel<<<1, 32>>>();
    minmax_kernel<<<512, 256>>>(q_, nQ, 0);
    minmax_kernel<<<512, 256>>>(k_, nE, 1);
    minmax_kernel<<<512, 256>>>(v_, nE, 2);
    quant_qk_kernel<<<dim3(32, BH), 256>>>(q_, qi_, SEQ, 1024, 0);
    quant_qk_kernel<<<dim3(4, BH), 256>>>(k_, ki_, SENC, 128, 1);
    quant_v_kernel<<<dim3(8, BH), 256>>>(v_, vi_, SENC, 128, 2);
    scores_mma_kernel<<<dim3(1, 8, BH), 256>>>(sc_, SENC, 128, premul);
    softmax_stats_kernel<<<NROWSBH, 128>>>(SENC);
    maxinv_kernel<<<64, 256>>>();
    quantp_kernel<<<NROWSBH, 256>>>(SENC, 128);
    pv_mma_kernel<<<dim3(8, BH), 256>>>(tc.ah, tc.al, 128);
    trans_W(Wo2, DMODEL, DMODEL, tc.bh, tc.bl);
    tc_gemm(tc, bo2, out, out, ROWS, DMODEL, DMODEL);

    // ================= feed-forward (GEGLU) =================
    ln_split_kernel<<<ROWS, 256>>>(out, ln3g, ln3b, tc.ah, tc.al);
    trans_W(Wff1, DMODEL, 2 * FFD, tc.bh, tc.bl);
    tc_gemm(tc, bff1, nullptr, pj_, ROWS, 2 * FFD, DMODEL);
    geglu_split_kernel<<<8192, 256>>>(tc.ah, tc.al);
    trans_W(Wff2, FFD, DMODEL, tc.bh, tc.bl);
    tc_gemm(tc, bff2, out, out, ROWS, DMODEL, FFD);
}